// round 9
// baseline (speedup 1.0000x reference)
#include <cuda_runtime.h>
#include <cuda_bf16.h>
#include <math.h>

#define BB   2
#define TT   1024
#define SS   2048
#define FF   1024
#define NN_  16
#define HH   64
#define MM   2049
#define NHD  1024

// ---- scratch (device globals; no allocations allowed) ----
static __device__ __nv_bfloat16 g_qu [BB*NN_*TT*HH];          // bf16(q + u_bias), [b][n][t][h]
static __device__ float         g_qv [BB*NN_*TT*HH];          // fp32 q + v_bias,  [b][n][t][h]
static __device__ __nv_bfloat16 g_kb [BB*NN_*SS*HH];          // bf16 k, [b][n][s][h]
static __device__ __nv_bfloat16 g_vb [BB*NN_*SS*HH];          // bf16 v, [b][n][s][h]
static __device__ float         g_r  [NN_*MM*HH];             // fp32 r, [n][m][h]
static __device__ float         g_lg [(size_t)BB*NN_*TT*SS];  // bias -> logits (256MB)
static __device__ float         g_max[BB*NN_*TT];             // softmax row max
static __device__ float         g_sum[BB*NN_*TT];             // softmax denominators
static __device__ __nv_bfloat16 g_ob [BB*TT*NHD];             // bf16 attention output, [b*t][n*h]

__device__ __forceinline__ unsigned pack_bf2(float a, float b) {
    __nv_bfloat162 p = __floats2bfloat162_rn(a, b);
    return *(unsigned*)&p;
}
__device__ __forceinline__ unsigned pack_u16(__nv_bfloat16 a, __nv_bfloat16 b) {
    unsigned short ua = *(unsigned short*)&a, ub2 = *(unsigned short*)&b;
    return (unsigned)ua | ((unsigned)ub2 << 16);
}

// ---- tf32 helpers ----
__device__ __forceinline__ unsigned f2tf(float f) {
    unsigned r;
    asm("cvt.rna.tf32.f32 %0, %1;" : "=r"(r) : "f"(f));
    return r;
}
__device__ __forceinline__ void tf_split_st4(float4 v, unsigned* ph, unsigned* pl) {
    unsigned h0 = f2tf(v.x), h1 = f2tf(v.y), h2 = f2tf(v.z), h3 = f2tf(v.w);
    float l0 = v.x - __uint_as_float(h0);
    float l1 = v.y - __uint_as_float(h1);
    float l2 = v.z - __uint_as_float(h2);
    float l3 = v.w - __uint_as_float(h3);
    *(uint4*)ph = make_uint4(h0, h1, h2, h3);
    *(uint4*)pl = make_uint4(f2tf(l0), f2tf(l1), f2tf(l2), f2tf(l3));
}

// ---- warp-level mma (plain sm_103-safe PTX) ----
__device__ __forceinline__ void mma16816(float* d,
                                         unsigned a0, unsigned a1, unsigned a2, unsigned a3,
                                         unsigned b0, unsigned b1) {
    asm volatile(
        "mma.sync.aligned.m16n8k16.row.col.f32.bf16.bf16.f32 "
        "{%0,%1,%2,%3}, {%4,%5,%6,%7}, {%8,%9}, {%0,%1,%2,%3};"
        : "+f"(d[0]), "+f"(d[1]), "+f"(d[2]), "+f"(d[3])
        : "r"(a0), "r"(a1), "r"(a2), "r"(a3), "r"(b0), "r"(b1));
}
__device__ __forceinline__ void mma_tf32(float* d,
                                         unsigned a0, unsigned a1, unsigned a2, unsigned a3,
                                         unsigned b0, unsigned b1) {
    asm volatile(
        "mma.sync.aligned.m16n8k8.row.col.f32.tf32.tf32.f32 "
        "{%0,%1,%2,%3}, {%4,%5,%6,%7}, {%8,%9}, {%0,%1,%2,%3};"
        : "+f"(d[0]), "+f"(d[1]), "+f"(d[2]), "+f"(d[3])
        : "r"(a0), "r"(a1), "r"(a2), "r"(a3), "r"(b0), "r"(b1));
}

// =====================================================================
// tf32-split GEMM skeleton: 128x128 tile, 8 warps (warp tile 64x32)
// =====================================================================
#define MMA_TILE_DECL() \
    const int tid = threadIdx.x, wid = tid >> 5, lane = tid & 31; \
    const int g = lane >> 2, tg = lane & 3; \
    const int m_base = (wid >> 2) * 64, n_base = (wid & 3) * 32; \
    float acc[4][4][4] = {};

#define TF_AFRAGS(af, Asm, kk) { _Pragma("unroll") for (int i_ = 0; i_ < 4; i_++) { \
    int mr_ = m_base + i_*16 + g; \
    af[i_][0] = Asm[mr_    ][(kk) + tg]; \
    af[i_][1] = Asm[mr_ + 8][(kk) + tg]; \
    af[i_][2] = Asm[mr_    ][(kk) + tg + 4]; \
    af[i_][3] = Asm[mr_ + 8][(kk) + tg + 4]; } }

#define TF_BFRAGS_KN(bf, Bsm, kk) { _Pragma("unroll") for (int j_ = 0; j_ < 4; j_++) { \
    int nr_ = n_base + j_*8 + g; \
    bf[j_][0] = Bsm[(kk) + tg    ][nr_]; \
    bf[j_][1] = Bsm[(kk) + tg + 4][nr_]; } }

#define TF_BFRAGS_NK(bf, Bsm, kk) { _Pragma("unroll") for (int j_ = 0; j_ < 4; j_++) { \
    int nr_ = n_base + j_*8 + g; \
    bf[j_][0] = Bsm[nr_][(kk) + tg]; \
    bf[j_][1] = Bsm[nr_][(kk) + tg + 4]; } }

#define TF_MMA(af, bf) { _Pragma("unroll") for (int i_ = 0; i_ < 4; i_++) \
    _Pragma("unroll") for (int j_ = 0; j_ < 4; j_++) \
        mma_tf32(acc[i_][j_], af[i_][0], af[i_][1], af[i_][2], af[i_][3], bf[j_][0], bf[j_][1]); }

// Mainloop: A fp32 [M][K] row-major (split), B fp32 [K][N] row-major (split)
#define PT_MAIN(APTR, LDA, ROWSLIM, BPTR, LDB, KDIM) \
    __shared__ unsigned Ah[128][20], Al[128][20]; \
    __shared__ unsigned Bh[16][132], Bl[16][132]; \
    { const int arow = tid >> 1, acol = (tid & 1) * 8; \
      const int brow = tid >> 4, bcol = (tid & 15) * 8; \
      for (int k0 = 0; k0 < (KDIM); k0 += 16) { \
        float4 va0 = make_float4(0.f,0.f,0.f,0.f), va1 = va0; \
        if (arow < (ROWSLIM)) { \
            va0 = *(const float4*)((APTR) + (size_t)arow * (LDA) + k0 + acol); \
            va1 = *(const float4*)((APTR) + (size_t)arow * (LDA) + k0 + acol + 4); \
        } \
        float4 vb0 = *(const float4*)((BPTR) + (size_t)(k0 + brow) * (LDB) + bcol); \
        float4 vb1 = *(const float4*)((BPTR) + (size_t)(k0 + brow) * (LDB) + bcol + 4); \
        tf_split_st4(va0, &Ah[arow][acol],     &Al[arow][acol]); \
        tf_split_st4(va1, &Ah[arow][acol + 4], &Al[arow][acol + 4]); \
        tf_split_st4(vb0, &Bh[brow][bcol],     &Bl[brow][bcol]); \
        tf_split_st4(vb1, &Bh[brow][bcol + 4], &Bl[brow][bcol + 4]); \
        __syncthreads(); \
        _Pragma("unroll") for (int kk = 0; kk < 16; kk += 8) { \
            unsigned af[4][4], bh[4][2], bl[4][2]; \
            TF_AFRAGS(af, Ah, kk); \
            TF_BFRAGS_KN(bh, Bh, kk); \
            TF_BFRAGS_KN(bl, Bl, kk); \
            TF_MMA(af, bh); \
            TF_MMA(af, bl); \
            TF_AFRAGS(af, Al, kk); \
            TF_MMA(af, bh); \
        } \
        __syncthreads(); \
      } }

// =====================================================================
// FFMA GEMM skeleton: 64(M) x 128(N) tile, 256 threads, 8x4 per thread,
// K-step 8. Exact fp32 numerics (sequential-K fmaf accumulation).
// =====================================================================
#define F64_DECL() \
    __shared__ float As[8][72]; \
    __shared__ float Bs[8][132]; \
    const int tid = threadIdx.x; \
    const int ty = tid >> 5, tx = tid & 31; \
    float acc[8][4] = {};

#define F64_LOAD_A(AP, LDA, KK, LIM) { \
    int r_ = tid >> 2, kc_ = (tid & 3) << 1; \
    float2 v_ = make_float2(0.f, 0.f); \
    if (r_ < (LIM)) v_ = *(const float2*)((AP) + (size_t)r_ * (LDA) + (KK) + kc_); \
    As[kc_][r_] = v_.x; As[kc_ + 1][r_] = v_.y; }

#define F64_LOAD_B_ROW(BP, LDB, KK) { \
    int kr_ = tid >> 5, c_ = (tid & 31) << 2; \
    float4 v_ = *(const float4*)((BP) + (size_t)((KK) + kr_) * (LDB) + c_); \
    *(float4*)&Bs[kr_][c_] = v_; }

#define F64_COMPUTE() { \
    _Pragma("unroll") \
    for (int k_ = 0; k_ < 8; k_++) { \
        float4 a0 = *(const float4*)&As[k_][ty * 8]; \
        float4 a1 = *(const float4*)&As[k_][ty * 8 + 4]; \
        float4 b  = *(const float4*)&Bs[k_][tx * 4]; \
        float av[8] = {a0.x, a0.y, a0.z, a0.w, a1.x, a1.y, a1.z, a1.w}; \
        float bv[4] = {b.x, b.y, b.z, b.w}; \
        _Pragma("unroll") for (int i_ = 0; i_ < 8; i_++) \
        _Pragma("unroll") for (int j_ = 0; j_ < 4; j_++) \
            acc[i_][j_] = fmaf(av[i_], bv[j_], acc[i_][j_]); \
    } }

// =====================================================================
// Projection q: x @ Wq -> qu bf16(+ub), qv fp32(+vb), BNTH  (exact FFMA)
// =====================================================================
__global__ void __launch_bounds__(256) rk_proj_q(const float* __restrict__ A,
                                                 const float* __restrict__ W,
                                                 const float* __restrict__ ub,
                                                 const float* __restrict__ vb)
{
    F64_DECL();
    const int row0 = blockIdx.x * 64, col0 = blockIdx.y * 128;
    const float* AP = A + (size_t)row0 * FF;
    for (int kk = 0; kk < FF; kk += 8) {
        F64_LOAD_A(AP, FF, kk, 1 << 30);
        F64_LOAD_B_ROW(W + col0, NHD, kk);
        __syncthreads();
        F64_COMPUTE();
        __syncthreads();
    }
    const int c0 = col0 + tx * 4;
    const int n = c0 >> 6, h = c0 & 63;
    float u0 = ub[c0], u1 = ub[c0+1], u2 = ub[c0+2], u3 = ub[c0+3];
    float v0 = vb[c0], v1 = vb[c0+1], v2 = vb[c0+2], v3 = vb[c0+3];
    #pragma unroll
    for (int i = 0; i < 8; i++) {
        int r = row0 + ty * 8 + i;
        int b_ = r >> 10, t = r & 1023;
        size_t o = ((size_t)(b_ * NN_ + n) * TT + t) * HH + h;
        *(uint2*)&g_qu[o] = make_uint2(pack_bf2(acc[i][0] + u0, acc[i][1] + u1),
                                       pack_bf2(acc[i][2] + u2, acc[i][3] + u3));
        *(float4*)&g_qv[o] = make_float4(acc[i][0] + v0, acc[i][1] + v1,
                                         acc[i][2] + v2, acc[i][3] + v3);
    }
}

// =====================================================================
// Projection k / v (dst selects), BNSH bf16  (exact FFMA)
// =====================================================================
__global__ void __launch_bounds__(256) rk_proj_kv(const float* __restrict__ A,
                                                  const float* __restrict__ W,
                                                  int which)
{
    F64_DECL();
    const int row0 = blockIdx.x * 64, col0 = blockIdx.y * 128;
    const float* AP = A + (size_t)row0 * FF;
    for (int kk = 0; kk < FF; kk += 8) {
        F64_LOAD_A(AP, FF, kk, 1 << 30);
        F64_LOAD_B_ROW(W + col0, NHD, kk);
        __syncthreads();
        F64_COMPUTE();
        __syncthreads();
    }
    __nv_bfloat16* dst = which ? g_vb : g_kb;
    const int c0 = col0 + tx * 4;
    const int n = c0 >> 6, h = c0 & 63;
    #pragma unroll
    for (int i = 0; i < 8; i++) {
        int r = row0 + ty * 8 + i;
        int b_ = r >> 11, s = r & 2047;
        size_t o = ((size_t)(b_ * NN_ + n) * SS + s) * HH + h;
        *(uint2*)&dst[o] = make_uint2(pack_bf2(acc[i][0], acc[i][1]),
                                      pack_bf2(acc[i][2], acc[i][3]));
    }
}

// =====================================================================
// Projection r: rel @ Wr -> fp32 [n][m][h]  (tf32-split; bias path is
// smooth downstream -> tolerant of split error)
// =====================================================================
__global__ void __launch_bounds__(256) rk_proj_r(const float* __restrict__ A,
                                                 const float* __restrict__ W)
{
    MMA_TILE_DECL();
    const int row0 = blockIdx.x * 128, col0 = blockIdx.y * 128;
    PT_MAIN(A + (size_t)row0 * FF, FF, MM - row0, W + col0, NHD, FF);
    #pragma unroll
    for (int i = 0; i < 4; i++) {
        int m0 = row0 + m_base + i * 16 + g;
        #pragma unroll
        for (int j = 0; j < 4; j++) {
            int c = col0 + n_base + j * 8 + tg * 2;
            int n = c >> 6, h = c & 63;
            #pragma unroll
            for (int hrow = 0; hrow < 2; hrow++) {
                int m = m0 + hrow * 8;
                if (m < MM) {
                    size_t o = ((size_t)n * MM + m) * HH + h;
                    *(float2*)&g_r[o] = make_float2(acc[i][j][hrow * 2], acc[i][j][hrow * 2 + 1]);
                }
            }
        }
    }
}

// =====================================================================
// final: y = fp32(out_b) @ Wout + b_out   (exact FFMA)
// =====================================================================
__global__ void __launch_bounds__(256) rk_out(const float* __restrict__ Wout,
                                              const float* __restrict__ bo,
                                              float* __restrict__ out)
{
    F64_DECL();
    const int row0 = blockIdx.x * 64, col0 = blockIdx.y * 128;
    const __nv_bfloat16* AP = g_ob + (size_t)row0 * NHD;
    for (int kk = 0; kk < NHD; kk += 8) {
        {
            int r_ = tid >> 2, kc_ = (tid & 3) << 1;
            unsigned w = *(const unsigned*)(AP + (size_t)r_ * NHD + kk + kc_);
            __nv_bfloat162 p = *(__nv_bfloat162*)&w;
            As[kc_][r_] = __low2float(p);
            As[kc_ + 1][r_] = __high2float(p);
        }
        F64_LOAD_B_ROW(Wout + col0, FF, kk);
        __syncthreads();
        F64_COMPUTE();
        __syncthreads();
    }
    const int c0 = col0 + tx * 4;
    float b0 = bo[c0], b1 = bo[c0+1], b2 = bo[c0+2], b3 = bo[c0+3];
    #pragma unroll
    for (int i = 0; i < 8; i++) {
        int r = row0 + ty * 8 + i;
        *(float4*)&out[(size_t)r * FF + c0] =
            make_float4(acc[i][0] + b0, acc[i][1] + b1, acc[i][2] + b2, acc[i][3] + b3);
    }
}

// =====================================================================
// bd = q_v @ r^T (tf32-split), scaled, scattered through the relative shift
// A = g_qv [t][h]; B = g_r [m][h] = [N][K] row-major. Smooth downstream.
// =====================================================================
__global__ void __launch_bounds__(256) rk_bd()
{
    MMA_TILE_DECL();
    const int bn = blockIdx.z;
    const int row0 = blockIdx.x * 128, col0 = blockIdx.y * 128;
    __shared__ unsigned Ah[128][20], Al[128][20];
    __shared__ unsigned Bh[128][20], Bl[128][20];
    const float* A  = g_qv + (size_t)bn * TT * HH + (size_t)row0 * HH;
    const float* Bt = g_r  + (size_t)(bn & 15) * MM * HH;
    const int arow = tid >> 1, acol = (tid & 1) * 8;
    const int blim = MM - col0;
    #pragma unroll
    for (int k0 = 0; k0 < HH; k0 += 16) {
        float4 va0 = *(const float4*)(A + (size_t)arow * HH + k0 + acol);
        float4 va1 = *(const float4*)(A + (size_t)arow * HH + k0 + acol + 4);
        float4 vb0 = make_float4(0.f,0.f,0.f,0.f), vb1 = vb0;
        if (arow < blim) {
            vb0 = *(const float4*)(Bt + (size_t)(col0 + arow) * HH + k0 + acol);
            vb1 = *(const float4*)(Bt + (size_t)(col0 + arow) * HH + k0 + acol + 4);
        }
        tf_split_st4(va0, &Ah[arow][acol],     &Al[arow][acol]);
        tf_split_st4(va1, &Ah[arow][acol + 4], &Al[arow][acol + 4]);
        tf_split_st4(vb0, &Bh[arow][acol],     &Bl[arow][acol]);
        tf_split_st4(vb1, &Bh[arow][acol + 4], &Bl[arow][acol + 4]);
        __syncthreads();
        #pragma unroll
        for (int kk = 0; kk < 16; kk += 8) {
            unsigned af[4][4], bh[4][2], bl[4][2];
            TF_AFRAGS(af, Ah, kk);
            TF_BFRAGS_NK(bh, Bh, kk);
            TF_BFRAGS_NK(bl, Bl, kk);
            TF_MMA(af, bh);
            TF_MMA(af, bl);
            TF_AFRAGS(af, Al, kk);
            TF_MMA(af, bh);
        }
        __syncthreads();
    }
    size_t base = (size_t)bn * TT * SS;
    #pragma unroll
    for (int i = 0; i < 4; i++) {
        int t0 = row0 + m_base + i * 16 + g;
        #pragma unroll
        for (int j = 0; j < 4; j++) {
            int m0 = col0 + n_base + j * 8 + tg * 2;
            #pragma unroll
            for (int e = 0; e < 4; e++) {
                int t = t0 + (e >> 1) * 8;
                int m = m0 + (e & 1);
                if (m < MM) {
                    float val = acc[i][j][e] * 0.125f;
                    int s1 = m + t - 1023;
                    if (s1 >= 0 && s1 < SS)
                        g_lg[base + (size_t)t * SS + s1] = val;
                    if (t >= 1) {
                        int s2 = m + t + 1026;
                        if (s2 < SS)
                            g_lg[base + (size_t)(t - 1) * SS + s2] = val;
                    }
                }
            }
        }
    }
}

// zero the d == 1026 diagonal (never written by the scatter)
__global__ void rk_zdiag()
{
    int bn = blockIdx.x;
    int t  = threadIdx.x;
    int s  = t + 1026;
    if (s < SS)
        g_lg[(size_t)bn*TT*SS + (size_t)t*SS + s] = 0.f;
}

// =====================================================================
// HMMA qk: logits[t,s] = bf16round(qk)*scale + bias  (RMW g_lg)
// =====================================================================
__global__ void __launch_bounds__(256) rk_qk_mma()
{
    __shared__ __nv_bfloat16 As[128][72];
    __shared__ __nv_bfloat16 Bs[128][72];
    const int tid = threadIdx.x, wid = tid >> 5, lane = tid & 31;
    const int g = lane >> 2, tg = lane & 3;
    const int bn = blockIdx.z;
    const int trow0 = blockIdx.x * 128, srow0 = blockIdx.y * 128;
    const int m_base = (wid >> 2) * 64, n_base = (wid & 3) * 32;

    {
        const __nv_bfloat16* Ag = g_qu + ((size_t)bn * TT + trow0) * HH;
        const __nv_bfloat16* Bg = g_kb + ((size_t)bn * SS + srow0) * HH;
        int r = tid >> 1, c0 = (tid & 1) * 32;
        const uint4* as = (const uint4*)(Ag + (size_t)r * HH + c0);
        const uint4* bs = (const uint4*)(Bg + (size_t)r * HH + c0);
        uint4* ad = (uint4*)&As[r][c0];
        uint4* bd = (uint4*)&Bs[r][c0];
        #pragma unroll
        for (int q = 0; q < 4; q++) { ad[q] = as[q]; bd[q] = bs[q]; }
    }
    __syncthreads();

    float acc[4][4][4] = {};
    #pragma unroll
    for (int kk = 0; kk < 64; kk += 16) {
        unsigned af[4][4], bf[4][2];
        #pragma unroll
        for (int i = 0; i < 4; i++) {
            int mr = m_base + i * 16 + g;
            af[i][0] = *(const unsigned*)&As[mr    ][kk + tg*2];
            af[i][1] = *(const unsigned*)&As[mr + 8][kk + tg*2];
            af[i][2] = *(const unsigned*)&As[mr    ][kk + 8 + tg*2];
            af[i][3] = *(const unsigned*)&As[mr + 8][kk + 8 + tg*2];
        }
        #pragma unroll
        for (int j = 0; j < 4; j++) {
            int nr = n_base + j * 8 + g;
            bf[j][0] = *(const unsigned*)&Bs[nr][kk + tg*2];
            bf[j][1] = *(const unsigned*)&Bs[nr][kk + 8 + tg*2];
        }
        #pragma unroll
        for (int i = 0; i < 4; i++)
            #pragma unroll
            for (int j = 0; j < 4; j++)
                mma16816(acc[i][j], af[i][0], af[i][1], af[i][2], af[i][3], bf[j][0], bf[j][1]);
    }

    size_t base = (size_t)bn * TT * SS;
    #pragma unroll
    for (int i = 0; i < 4; i++) {
        int t0 = trow0 + m_base + i * 16 + g;
        #pragma unroll
        for (int j = 0; j < 4; j++) {
            int s = srow0 + n_base + j * 8 + tg * 2;
            float q00 = __bfloat162float(__float2bfloat16(acc[i][j][0])) * 0.125f;
            float q01 = __bfloat162float(__float2bfloat16(acc[i][j][1])) * 0.125f;
            float q10 = __bfloat162float(__float2bfloat16(acc[i][j][2])) * 0.125f;
            float q11 = __bfloat162float(__float2bfloat16(acc[i][j][3])) * 0.125f;
            float2* p0 = (float2*)&g_lg[base + (size_t)t0 * SS + s];
            float2* p1 = (float2*)&g_lg[base + (size_t)(t0 + 8) * SS + s];
            float2 v0 = *p0, v1 = *p1;
            v0.x += q00; v0.y += q01;
            v1.x += q10; v1.y += q11;
            *p0 = v0; *p1 = v1;
        }
    }
}

// =====================================================================
// softmax stats: per row max + sum(exp(l - max)), single read of logits
// =====================================================================
__global__ void __launch_bounds__(256) rk_stats()
{
    const int row = blockIdx.x;
    const float* p = g_lg + (size_t)row * SS;
    __shared__ float red[256];
    const int tid = threadIdx.x;
    float r[8];
    #pragma unroll
    for (int w = 0; w < 8; w++) r[w] = p[tid + 256 * w];
    float m = r[0];
    #pragma unroll
    for (int w = 1; w < 8; w++) m = fmaxf(m, r[w]);
    red[tid] = m; __syncthreads();
    for (int off = 128; off > 0; off >>= 1) {
        if (tid < off) red[tid] = fmaxf(red[tid], red[tid + off]);
        __syncthreads();
    }
    m = red[0];
    __syncthreads();
    float s = 0.f;
    #pragma unroll
    for (int w = 0; w < 8; w++) s += expf(r[w] - m);
    red[tid] = s; __syncthreads();
    for (int off = 128; off > 0; off >>= 1) {
        if (tid < off) red[tid] += red[tid + off];
        __syncthreads();
    }
    if (tid == 0) { g_max[row] = m; g_sum[row] = red[0]; }
}

// =====================================================================
// HMMA pv: out[t,h] = bf16(probs) @ v. tile 128(t) x 64(h), K=2048 in 64-chunks.
// =====================================================================
__global__ void __launch_bounds__(256) rk_pv_mma()
{
    __shared__ __nv_bfloat16 As[128][72];
    __shared__ __nv_bfloat16 Bs[64][72];
    __shared__ float s_max[128], s_sum[128];
    const int tid = threadIdx.x, wid = tid >> 5, lane = tid & 31;
    const int g = lane >> 2, tg = lane & 3;
    const int bn = blockIdx.z;
    const int trow0 = blockIdx.x * 128;
    const int m_base = (wid >> 1) * 32, n_base = (wid & 1) * 32;

    if (tid < 128) {
        s_max[tid] = g_max[bn * TT + trow0 + tid];
        s_sum[tid] = g_sum[bn * TT + trow0 + tid];
    }
    __syncthreads();

    const float* Lg = g_lg + (size_t)bn * TT * SS + (size_t)trow0 * SS;
    const __nv_bfloat16* Vg = g_vb + (size_t)bn * SS * HH;
    const int prow = tid >> 1, pc0 = (tid & 1) * 32;
    const float mrow = s_max[prow], srow = s_sum[prow];
    const int vrow = tid >> 2, vc0 = (tid & 3) * 16;

    float acc[2][4][4] = {};
    for (int ck = 0; ck < 32; ck++) {
        const int s0 = ck * 64;
        __syncthreads();
        {
            const float4* lp = (const float4*)(Lg + (size_t)prow * SS + s0 + pc0);
            unsigned pw[16];
            #pragma unroll
            for (int q = 0; q < 8; q++) {
                float4 x = lp[q];
                float u0 = __fdiv_rn(expf(x.x - mrow), srow);
                float u1 = __fdiv_rn(expf(x.y - mrow), srow);
                float u2 = __fdiv_rn(expf(x.z - mrow), srow);
                float u3 = __fdiv_rn(expf(x.w - mrow), srow);
                pw[q*2]   = pack_bf2(u0, u1);
                pw[q*2+1] = pack_bf2(u2, u3);
            }
            uint4* dst = (uint4*)&As[prow][pc0];
            #pragma unroll
            for (int q = 0; q < 4; q++)
                dst[q] = make_uint4(pw[q*4], pw[q*4+1], pw[q*4+2], pw[q*4+3]);
        }
        {
            const uint4* vp = (const uint4*)(Vg + (size_t)(s0 + vrow) * HH + vc0);
            uint4* dst = (uint4*)&Bs[vrow][vc0];
            dst[0] = vp[0];
            dst[1] = vp[1];
        }
        __syncthreads();
        #pragma unroll
        for (int kk = 0; kk < 64; kk += 16) {
            unsigned af[2][4], bf[4][2];
            #pragma unroll
            for (int i = 0; i < 2; i++) {
                int mr = m_base + i * 16 + g;
                af[i][0] = *(const unsigned*)&As[mr    ][kk + tg*2];
                af[i][1] = *(const unsigned*)&As[mr + 8][kk + tg*2];
                af[i][2] = *(const unsigned*)&As[mr    ][kk + 8 + tg*2];
                af[i][3] = *(const unsigned*)&As[mr + 8][kk + 8 + tg*2];
            }
            #pragma unroll
            for (int j = 0; j < 4; j++) {
                int nr = n_base + j * 8 + g;
                bf[j][0] = pack_u16(Bs[kk + tg*2][nr],     Bs[kk + tg*2 + 1][nr]);
                bf[j][1] = pack_u16(Bs[kk + 8 + tg*2][nr], Bs[kk + 8 + tg*2 + 1][nr]);
            }
            #pragma unroll
            for (int i = 0; i < 2; i++)
                #pragma unroll
                for (int j = 0; j < 4; j++)
                    mma16816(acc[i][j], af[i][0], af[i][1], af[i][2], af[i][3], bf[j][0], bf[j][1]);
        }
    }

    const int b_ = bn >> 4, n = bn & 15;
    #pragma unroll
    for (int i = 0; i < 2; i++) {
        int t0 = trow0 + m_base + i * 16 + g;
        #pragma unroll
        for (int j = 0; j < 4; j++) {
            int h = n_base + j * 8 + tg * 2;
            *(unsigned*)&g_ob[(size_t)(b_ * TT + t0    ) * NHD + n * HH + h] =
                pack_bf2(acc[i][j][0], acc[i][j][1]);
            *(unsigned*)&g_ob[(size_t)(b_ * TT + t0 + 8) * NHD + n * HH + h] =
                pack_bf2(acc[i][j][2], acc[i][j][3]);
        }
    }
}

extern "C" void kernel_launch(void* const* d_in, const int* in_sizes, int n_in,
                              void* d_out, int out_size)
{
    (void)in_sizes; (void)n_in; (void)out_size;
    const float* x    = (const float*)d_in[0];
    const float* rel  = (const float*)d_in[1];
    const float* mem  = (const float*)d_in[2];
    const float* Wq   = (const float*)d_in[3];
    const float* Wk   = (const float*)d_in[4];
    const float* Wv   = (const float*)d_in[5];
    const float* Wr   = (const float*)d_in[6];
    const float* ub   = (const float*)d_in[7];
    const float* vb   = (const float*)d_in[8];
    const float* Wout = (const float*)d_in[9];
    const float* bo   = (const float*)d_in[10];
    float* out = (float*)d_out;

    rk_proj_q <<<dim3(BB*TT/64, NHD/128), 256>>>(x, Wq, ub, vb);
    rk_proj_kv<<<dim3(BB*SS/64, NHD/128), 256>>>(mem, Wk, 0);
    rk_proj_kv<<<dim3(BB*SS/64, NHD/128), 256>>>(mem, Wv, 1);
    rk_proj_r <<<dim3((MM+127)/128, NHD/128), 256>>>(rel, Wr);
    rk_bd     <<<dim3(TT/128, (MM+127)/128, BB*NN_), 256>>>();
    rk_zdiag  <<<BB*NN_, TT>>>();
    rk_qk_mma <<<dim3(TT/128, SS/128, BB*NN_), 256>>>();
    rk_stats  <<<BB*NN_*TT, 256>>>();
    rk_pv_mma <<<dim3(TT/128, 1, BB*NN_), 256>>>();
    rk_out    <<<dim3(BB*TT/64, FF/128), 256>>>(Wout, bo, out);
}

// round 10
// speedup vs baseline: 1.5609x; 1.5609x over previous
#include <cuda_runtime.h>
#include <cuda_bf16.h>
#include <math.h>

#define BB   2
#define TT   1024
#define SS   2048
#define FF   1024
#define NN_  16
#define HH   64
#define MM   2049
#define NHD  1024

// ---- scratch (device globals; no allocations allowed) ----
static __device__ __nv_bfloat16 g_qu [BB*NN_*TT*HH];          // bf16(q + u_bias), [b][n][t][h]
static __device__ float         g_qv [BB*NN_*TT*HH];          // fp32 q + v_bias,  [b][n][t][h]
static __device__ __nv_bfloat16 g_kb [BB*NN_*SS*HH];          // bf16 k, [b][n][s][h]
static __device__ __nv_bfloat16 g_vb [BB*NN_*SS*HH];          // bf16 v, [b][n][s][h]
static __device__ float         g_r  [NN_*MM*HH];             // fp32 r, [n][m][h]
static __device__ float         g_lg [(size_t)BB*NN_*TT*SS];  // bias -> logits (256MB)
static __device__ float         g_max[BB*NN_*TT];             // softmax row max
static __device__ float         g_sum[BB*NN_*TT];             // softmax denominators
static __device__ __nv_bfloat16 g_ob [BB*TT*NHD];             // bf16 attention output, [b*t][n*h]

__device__ __forceinline__ unsigned pack_bf2(float a, float b) {
    __nv_bfloat162 p = __floats2bfloat162_rn(a, b);
    return *(unsigned*)&p;
}
__device__ __forceinline__ unsigned pack_u16(__nv_bfloat16 a, __nv_bfloat16 b) {
    unsigned short ua = *(unsigned short*)&a, ub2 = *(unsigned short*)&b;
    return (unsigned)ua | ((unsigned)ub2 << 16);
}

// ---- warp-level bf16 tensor-core mma (plain sm_103-safe PTX) ----
__device__ __forceinline__ void mma16816(float* d,
                                         unsigned a0, unsigned a1, unsigned a2, unsigned a3,
                                         unsigned b0, unsigned b1) {
    asm volatile(
        "mma.sync.aligned.m16n8k16.row.col.f32.bf16.bf16.f32 "
        "{%0,%1,%2,%3}, {%4,%5,%6,%7}, {%8,%9}, {%0,%1,%2,%3};"
        : "+f"(d[0]), "+f"(d[1]), "+f"(d[2]), "+f"(d[3])
        : "r"(a0), "r"(a1), "r"(a2), "r"(a3), "r"(b0), "r"(b1));
}

// =====================================================================
// FFMA GEMM skeleton: 64(M) x 128(N) tile, 256 threads, 8x4 per thread,
// K-step 8, DOUBLE-BUFFERED smem with register staging (1 sync / iter).
// Exact fp32 numerics (sequential-K fmaf accumulation, same order as R8).
// =====================================================================
#define F64_DECL() \
    __shared__ float As[2][8][72]; \
    __shared__ float Bs[2][8][132]; \
    const int tid = threadIdx.x; \
    const int ty = tid >> 5, tx = tid & 31; \
    const int a_r = tid >> 2, a_k = (tid & 3) << 1; \
    const int b_k = tid >> 5, b_c = (tid & 31) << 2; \
    float acc[8][4] = {}; \
    float2 ra; float4 rb;

// A fp32 row-major [M][K]; AP = base + row0*LDA; guarded by LIM rows
#define F64_LDG_A(AP, LDA, KK, LIM) { \
    ra = make_float2(0.f, 0.f); \
    if (a_r < (LIM)) ra = *(const float2*)((AP) + (size_t)a_r * (LDA) + (KK) + a_k); }

#define F64_STS_A(bi) { As[bi][a_k][a_r] = ra.x; As[bi][a_k + 1][a_r] = ra.y; }

// B fp32 row-major [K][N]; BP = base + col0
#define F64_LDG_B(BP, LDB, KK) { \
    rb = *(const float4*)((BP) + (size_t)((KK) + b_k) * (LDB) + b_c); }

#define F64_STS_B(bi) { *(float4*)&Bs[bi][b_k][b_c] = rb; }

#define F64_COMPUTE(bi) { \
    _Pragma("unroll") \
    for (int k_ = 0; k_ < 8; k_++) { \
        float4 a0 = *(const float4*)&As[bi][k_][ty * 8]; \
        float4 a1 = *(const float4*)&As[bi][k_][ty * 8 + 4]; \
        float4 b  = *(const float4*)&Bs[bi][k_][tx * 4]; \
        float av[8] = {a0.x, a0.y, a0.z, a0.w, a1.x, a1.y, a1.z, a1.w}; \
        float bv[4] = {b.x, b.y, b.z, b.w}; \
        _Pragma("unroll") for (int i_ = 0; i_ < 8; i_++) \
        _Pragma("unroll") for (int j_ = 0; j_ < 4; j_++) \
            acc[i_][j_] = fmaf(av[i_], bv[j_], acc[i_][j_]); \
    } }

// Double-buffered mainloop: A fp32, B row-major fp32
#define F64_MAIN(AP, LDA, ALIM, BP, LDB, KDIM) { \
    F64_LDG_A(AP, LDA, 0, ALIM); \
    F64_LDG_B(BP, LDB, 0); \
    F64_STS_A(0); F64_STS_B(0); \
    __syncthreads(); \
    const int nIt = (KDIM) / 8; \
    for (int it = 0; it < nIt; it++) { \
        if (it + 1 < nIt) { \
            F64_LDG_A(AP, LDA, (it + 1) * 8, ALIM); \
            F64_LDG_B(BP, LDB, (it + 1) * 8); \
        } \
        F64_COMPUTE(it & 1); \
        if (it + 1 < nIt) { F64_STS_A((it + 1) & 1); F64_STS_B((it + 1) & 1); } \
        __syncthreads(); \
    } }

// =====================================================================
// Projection q: x @ Wq -> qu bf16(+ub), qv fp32(+vb), BNTH
// =====================================================================
__global__ void __launch_bounds__(256) rk_proj_q(const float* __restrict__ A,
                                                 const float* __restrict__ W,
                                                 const float* __restrict__ ub,
                                                 const float* __restrict__ vb)
{
    F64_DECL();
    const int row0 = blockIdx.x * 64, col0 = blockIdx.y * 128;
    F64_MAIN(A + (size_t)row0 * FF, FF, 1 << 30, W + col0, NHD, FF);
    const int c0 = col0 + tx * 4;
    const int n = c0 >> 6, h = c0 & 63;
    float u0 = ub[c0], u1 = ub[c0+1], u2 = ub[c0+2], u3 = ub[c0+3];
    float v0 = vb[c0], v1 = vb[c0+1], v2 = vb[c0+2], v3 = vb[c0+3];
    #pragma unroll
    for (int i = 0; i < 8; i++) {
        int r = row0 + ty * 8 + i;
        int b_ = r >> 10, t = r & 1023;
        size_t o = ((size_t)(b_ * NN_ + n) * TT + t) * HH + h;
        *(uint2*)&g_qu[o] = make_uint2(pack_bf2(acc[i][0] + u0, acc[i][1] + u1),
                                       pack_bf2(acc[i][2] + u2, acc[i][3] + u3));
        *(float4*)&g_qv[o] = make_float4(acc[i][0] + v0, acc[i][1] + v1,
                                         acc[i][2] + v2, acc[i][3] + v3);
    }
}

// =====================================================================
// Projection k / v (dst selects), BNSH bf16
// =====================================================================
__global__ void __launch_bounds__(256) rk_proj_kv(const float* __restrict__ A,
                                                  const float* __restrict__ W,
                                                  int which)
{
    F64_DECL();
    const int row0 = blockIdx.x * 64, col0 = blockIdx.y * 128;
    F64_MAIN(A + (size_t)row0 * FF, FF, 1 << 30, W + col0, NHD, FF);
    __nv_bfloat16* dst = which ? g_vb : g_kb;
    const int c0 = col0 + tx * 4;
    const int n = c0 >> 6, h = c0 & 63;
    #pragma unroll
    for (int i = 0; i < 8; i++) {
        int r = row0 + ty * 8 + i;
        int b_ = r >> 11, s = r & 2047;
        size_t o = ((size_t)(b_ * NN_ + n) * SS + s) * HH + h;
        *(uint2*)&dst[o] = make_uint2(pack_bf2(acc[i][0], acc[i][1]),
                                      pack_bf2(acc[i][2], acc[i][3]));
    }
}

// =====================================================================
// Projection r (M=2049 guard), fp32 [n][m][h]
// =====================================================================
__global__ void __launch_bounds__(256) rk_proj_r(const float* __restrict__ A,
                                                 const float* __restrict__ W)
{
    F64_DECL();
    const int row0 = blockIdx.x * 64, col0 = blockIdx.y * 128;
    const int lim = MM - row0;
    F64_MAIN(A + (size_t)row0 * FF, FF, lim, W + col0, NHD, FF);
    const int c0 = col0 + tx * 4;
    const int n = c0 >> 6, h = c0 & 63;
    #pragma unroll
    for (int i = 0; i < 8; i++) {
        int m = row0 + ty * 8 + i;
        if (m >= MM) continue;
        size_t o = ((size_t)n * MM + m) * HH + h;
        *(float4*)&g_r[o] = make_float4(acc[i][0], acc[i][1], acc[i][2], acc[i][3]);
    }
}

// =====================================================================
// final: y = fp32(out_b) @ Wout + b_out   (A is bf16 -> upconvert in load)
// =====================================================================
__global__ void __launch_bounds__(256) rk_out(const float* __restrict__ Wout,
                                              const float* __restrict__ bo,
                                              float* __restrict__ out)
{
    F64_DECL();
    const int row0 = blockIdx.x * 64, col0 = blockIdx.y * 128;
    const __nv_bfloat16* AP = g_ob + (size_t)row0 * NHD;
    // A loader (bf16): stage raw word in ra.x's bits
    unsigned raw;
    {
        raw = *(const unsigned*)(AP + (size_t)a_r * NHD + 0 + a_k);
        __nv_bfloat162 p = *(__nv_bfloat162*)&raw;
        As[0][a_k][a_r] = __low2float(p); As[0][a_k + 1][a_r] = __high2float(p);
    }
    F64_LDG_B(Wout + col0, FF, 0);
    F64_STS_B(0);
    __syncthreads();
    const int nIt = NHD / 8;
    for (int it = 0; it < nIt; it++) {
        unsigned nraw = 0;
        if (it + 1 < nIt) {
            nraw = *(const unsigned*)(AP + (size_t)a_r * NHD + (it + 1) * 8 + a_k);
            F64_LDG_B(Wout + col0, FF, (it + 1) * 8);
        }
        F64_COMPUTE(it & 1);
        if (it + 1 < nIt) {
            int bi = (it + 1) & 1;
            __nv_bfloat162 p = *(__nv_bfloat162*)&nraw;
            As[bi][a_k][a_r] = __low2float(p); As[bi][a_k + 1][a_r] = __high2float(p);
            F64_STS_B(bi);
        }
        __syncthreads();
    }
    const int c0 = col0 + tx * 4;
    float b0 = bo[c0], b1 = bo[c0+1], b2 = bo[c0+2], b3 = bo[c0+3];
    #pragma unroll
    for (int i = 0; i < 8; i++) {
        int r = row0 + ty * 8 + i;
        *(float4*)&out[(size_t)r * FF + c0] =
            make_float4(acc[i][0] + b0, acc[i][1] + b1, acc[i][2] + b2, acc[i][3] + b3);
    }
}

// =====================================================================
// bd = q_v @ r^T per (b,n), scaled, scattered through the relative shift
// B loaded transposed from [N][K]=g_r rows. Double-buffered like F64_MAIN.
// =====================================================================
__global__ void __launch_bounds__(256) rk_bd()
{
    F64_DECL();
    const int bn = blockIdx.z;
    const int row0 = blockIdx.x * 64, col0 = blockIdx.y * 128;
    const float* AP = g_qv + (size_t)bn * TT * HH + (size_t)row0 * HH;
    const float* BT = g_r  + (size_t)(bn & 15) * MM * HH + (size_t)col0 * HH;
    const int lim = MM - col0;
    const int t_n = tid >> 1, t_k = (tid & 1) << 2;   // B-transpose loader indices
    float4 rbt;
    // prologue k=0
    F64_LDG_A(AP, HH, 0, 1 << 30);
    rbt = make_float4(0.f, 0.f, 0.f, 0.f);
    if (t_n < lim) rbt = *(const float4*)(BT + (size_t)t_n * HH + 0 + t_k);
    F64_STS_A(0);
    Bs[0][t_k + 0][t_n] = rbt.x; Bs[0][t_k + 1][t_n] = rbt.y;
    Bs[0][t_k + 2][t_n] = rbt.z; Bs[0][t_k + 3][t_n] = rbt.w;
    __syncthreads();
    const int nIt = HH / 8;
    #pragma unroll
    for (int it = 0; it < nIt; it++) {
        if (it + 1 < nIt) {
            F64_LDG_A(AP, HH, (it + 1) * 8, 1 << 30);
            rbt = make_float4(0.f, 0.f, 0.f, 0.f);
            if (t_n < lim) rbt = *(const float4*)(BT + (size_t)t_n * HH + (it + 1) * 8 + t_k);
        }
        F64_COMPUTE(it & 1);
        if (it + 1 < nIt) {
            int bi = (it + 1) & 1;
            F64_STS_A(bi);
            Bs[bi][t_k + 0][t_n] = rbt.x; Bs[bi][t_k + 1][t_n] = rbt.y;
            Bs[bi][t_k + 2][t_n] = rbt.z; Bs[bi][t_k + 3][t_n] = rbt.w;
        }
        __syncthreads();
    }
    size_t base = (size_t)bn * TT * SS;
    #pragma unroll
    for (int i = 0; i < 8; i++) {
        int t = row0 + ty * 8 + i;
        #pragma unroll
        for (int j = 0; j < 4; j++) {
            int m = col0 + tx * 4 + j;
            if (m < MM) {
                float val = acc[i][j] * 0.125f;
                int s1 = m + t - 1023;
                if (s1 >= 0 && s1 < SS)
                    g_lg[base + (size_t)t * SS + s1] = val;
                if (t >= 1) {
                    int s2 = m + t + 1026;
                    if (s2 < SS)
                        g_lg[base + (size_t)(t - 1) * SS + s2] = val;
                }
            }
        }
    }
}

// zero the d == 1026 diagonal (never written by the scatter)
__global__ void rk_zdiag()
{
    int bn = blockIdx.x;
    int t  = threadIdx.x;
    int s  = t + 1026;
    if (s < SS)
        g_lg[(size_t)bn*TT*SS + (size_t)t*SS + s] = 0.f;
}

// =====================================================================
// HMMA qk: logits[t,s] = bf16round(qk)*scale + bias  (RMW g_lg)
// tile 128(t) x 128(s), K=64. 8 warps: warp tile 64x32.  (R4-proven)
// =====================================================================
__global__ void __launch_bounds__(256) rk_qk_mma()
{
    __shared__ __nv_bfloat16 As[128][72];
    __shared__ __nv_bfloat16 Bs[128][72];
    const int tid = threadIdx.x, wid = tid >> 5, lane = tid & 31;
    const int g = lane >> 2, tg = lane & 3;
    const int bn = blockIdx.z;
    const int trow0 = blockIdx.x * 128, srow0 = blockIdx.y * 128;
    const int m_base = (wid >> 2) * 64, n_base = (wid & 3) * 32;

    {
        const __nv_bfloat16* Ag = g_qu + ((size_t)bn * TT + trow0) * HH;
        const __nv_bfloat16* Bg = g_kb + ((size_t)bn * SS + srow0) * HH;
        int r = tid >> 1, c0 = (tid & 1) * 32;
        const uint4* as = (const uint4*)(Ag + (size_t)r * HH + c0);
        const uint4* bs = (const uint4*)(Bg + (size_t)r * HH + c0);
        uint4* ad = (uint4*)&As[r][c0];
        uint4* bd = (uint4*)&Bs[r][c0];
        #pragma unroll
        for (int q = 0; q < 4; q++) { ad[q] = as[q]; bd[q] = bs[q]; }
    }
    __syncthreads();

    float acc[4][4][4] = {};
    #pragma unroll
    for (int kk = 0; kk < 64; kk += 16) {
        unsigned af[4][4], bf[4][2];
        #pragma unroll
        for (int i = 0; i < 4; i++) {
            int mr = m_base + i * 16 + g;
            af[i][0] = *(const unsigned*)&As[mr    ][kk + tg*2];
            af[i][1] = *(const unsigned*)&As[mr + 8][kk + tg*2];
            af[i][2] = *(const unsigned*)&As[mr    ][kk + 8 + tg*2];
            af[i][3] = *(const unsigned*)&As[mr + 8][kk + 8 + tg*2];
        }
        #pragma unroll
        for (int j = 0; j < 4; j++) {
            int nr = n_base + j * 8 + g;
            bf[j][0] = *(const unsigned*)&Bs[nr][kk + tg*2];
            bf[j][1] = *(const unsigned*)&Bs[nr][kk + 8 + tg*2];
        }
        #pragma unroll
        for (int i = 0; i < 4; i++)
            #pragma unroll
            for (int j = 0; j < 4; j++)
                mma16816(acc[i][j], af[i][0], af[i][1], af[i][2], af[i][3], bf[j][0], bf[j][1]);
    }

    size_t base = (size_t)bn * TT * SS;
    #pragma unroll
    for (int i = 0; i < 4; i++) {
        int t0 = trow0 + m_base + i * 16 + g;
        #pragma unroll
        for (int j = 0; j < 4; j++) {
            int s = srow0 + n_base + j * 8 + tg * 2;
            float q00 = __bfloat162float(__float2bfloat16(acc[i][j][0])) * 0.125f;
            float q01 = __bfloat162float(__float2bfloat16(acc[i][j][1])) * 0.125f;
            float q10 = __bfloat162float(__float2bfloat16(acc[i][j][2])) * 0.125f;
            float q11 = __bfloat162float(__float2bfloat16(acc[i][j][3])) * 0.125f;
            float2* p0 = (float2*)&g_lg[base + (size_t)t0 * SS + s];
            float2* p1 = (float2*)&g_lg[base + (size_t)(t0 + 8) * SS + s];
            float2 v0 = *p0, v1 = *p1;
            v0.x += q00; v0.y += q01;
            v1.x += q10; v1.y += q11;
            *p0 = v0; *p1 = v1;
        }
    }
}

// =====================================================================
// softmax stats: per row max + sum(exp(l - max)), single read of logits
// =====================================================================
__global__ void __launch_bounds__(256) rk_stats()
{
    const int row = blockIdx.x;
    const float* p = g_lg + (size_t)row * SS;
    __shared__ float red[256];
    const int tid = threadIdx.x;
    float r[8];
    #pragma unroll
    for (int w = 0; w < 8; w++) r[w] = p[tid + 256 * w];
    float m = r[0];
    #pragma unroll
    for (int w = 1; w < 8; w++) m = fmaxf(m, r[w]);
    red[tid] = m; __syncthreads();
    for (int off = 128; off > 0; off >>= 1) {
        if (tid < off) red[tid] = fmaxf(red[tid], red[tid + off]);
        __syncthreads();
    }
    m = red[0];
    __syncthreads();
    float s = 0.f;
    #pragma unroll
    for (int w = 0; w < 8; w++) s += expf(r[w] - m);
    red[tid] = s; __syncthreads();
    for (int off = 128; off > 0; off >>= 1) {
        if (tid < off) red[tid] += red[tid + off];
        __syncthreads();
    }
    if (tid == 0) { g_max[row] = m; g_sum[row] = red[0]; }
}

// =====================================================================
// HMMA pv: out[t,h] = bf16(probs) @ v. tile 128(t) x 64(h), K=2048 in 64-chunks.
// B fragments gathered k-major from g_vb [s][h].  (bf16-exact path)
// =====================================================================
__global__ void __launch_bounds__(256) rk_pv_mma()
{
    __shared__ __nv_bfloat16 As[128][72];
    __shared__ __nv_bfloat16 Bs[64][72];
    __shared__ float s_max[128], s_sum[128];
    const int tid = threadIdx.x, wid = tid >> 5, lane = tid & 31;
    const int g = lane >> 2, tg = lane & 3;
    const int bn = blockIdx.z;
    const int trow0 = blockIdx.x * 128;
    const int m_base = (wid >> 1) * 32, n_base = (wid & 1) * 32;

    if (tid < 128) {
        s_max[tid] = g_max[bn * TT + trow0 + tid];
        s_sum[tid] = g_sum[bn * TT + trow0 + tid];
    }
    __syncthreads();

    const float* Lg = g_lg + (size_t)bn * TT * SS + (size_t)trow0 * SS;
    const __nv_bfloat16* Vg = g_vb + (size_t)bn * SS * HH;
    const int prow = tid >> 1, pc0 = (tid & 1) * 32;
    const float mrow = s_max[prow], srow = s_sum[prow];
    const int vrow = tid >> 2, vc0 = (tid & 3) * 16;

    float acc[2][4][4] = {};
    for (int ck = 0; ck < 32; ck++) {
        const int s0 = ck * 64;
        __syncthreads();
        {
            const float4* lp = (const float4*)(Lg + (size_t)prow * SS + s0 + pc0);
            unsigned pw[16];
            #pragma unroll
            for (int q = 0; q < 8; q++) {
                float4 x = lp[q];
                float u0 = __fdiv_rn(expf(x.x - mrow), srow);
                float u1 = __fdiv_rn(expf(x.y - mrow), srow);
                float u2 = __fdiv_rn(expf(x.z - mrow), srow);
                float u3 = __fdiv_rn(expf(x.w - mrow), srow);
                pw[q*2]   = pack_bf2(u0, u1);
                pw[q*2+1] = pack_bf2(u2, u3);
            }
            uint4* dst = (uint4*)&As[prow][pc0];
            #pragma unroll
            for (int q = 0; q < 4; q++)
                dst[q] = make_uint4(pw[q*4], pw[q*4+1], pw[q*4+2], pw[q*4+3]);
        }
        {
            const uint4* vp = (const uint4*)(Vg + (size_t)(s0 + vrow) * HH + vc0);
            uint4* dst = (uint4*)&Bs[vrow][vc0];
            dst[0] = vp[0];
            dst[1] = vp[1];
        }
        __syncthreads();
        #pragma unroll
        for (int kk = 0; kk < 64; kk += 16) {
            unsigned af[2][4], bf[4][2];
            #pragma unroll
            for (int i = 0; i < 2; i++) {
                int mr = m_base + i * 16 + g;
                af[i][0] = *(const unsigned*)&As[mr    ][kk + tg*2];
                af[i][1] = *(const unsigned*)&As[mr + 8][kk + tg*2];
                af[i][2] = *(const unsigned*)&As[mr    ][kk + 8 + tg*2];
                af[i][3] = *(const unsigned*)&As[mr + 8][kk + 8 + tg*2];
            }
            #pragma unroll
            for (int j = 0; j < 4; j++) {
                int nr = n_base + j * 8 + g;
                bf[j][0] = pack_u16(Bs[kk + tg*2][nr],     Bs[kk + tg*2 + 1][nr]);
                bf[j][1] = pack_u16(Bs[kk + 8 + tg*2][nr], Bs[kk + 8 + tg*2 + 1][nr]);
            }
            #pragma unroll
            for (int i = 0; i < 2; i++)
                #pragma unroll
                for (int j = 0; j < 4; j++)
                    mma16816(acc[i][j], af[i][0], af[i][1], af[i][2], af[i][3], bf[j][0], bf[j][1]);
        }
    }

    const int b_ = bn >> 4, n = bn & 15;
    #pragma unroll
    for (int i = 0; i < 2; i++) {
        int t0 = trow0 + m_base + i * 16 + g;
        #pragma unroll
        for (int j = 0; j < 4; j++) {
            int h = n_base + j * 8 + tg * 2;
            *(unsigned*)&g_ob[(size_t)(b_ * TT + t0    ) * NHD + n * HH + h] =
                pack_bf2(acc[i][j][0], acc[i][j][1]);
            *(unsigned*)&g_ob[(size_t)(b_ * TT + t0 + 8) * NHD + n * HH + h] =
                pack_bf2(acc[i][j][2], acc[i][j][3]);
        }
    }
}

extern "C" void kernel_launch(void* const* d_in, const int* in_sizes, int n_in,
                              void* d_out, int out_size)
{
    (void)in_sizes; (void)n_in; (void)out_size;
    const float* x    = (const float*)d_in[0];
    const float* rel  = (const float*)d_in[1];
    const float* mem  = (const float*)d_in[2];
    const float* Wq   = (const float*)d_in[3];
    const float* Wk   = (const float*)d_in[4];
    const float* Wv   = (const float*)d_in[5];
    const float* Wr   = (const float*)d_in[6];
    const float* ub   = (const float*)d_in[7];
    const float* vb   = (const float*)d_in[8];
    const float* Wout = (const float*)d_in[9];
    const float* bo   = (const float*)d_in[10];
    float* out = (float*)d_out;

    rk_proj_q <<<dim3(BB*TT/64, NHD/128), 256>>>(x, Wq, ub, vb);
    rk_proj_kv<<<dim3(BB*SS/64, NHD/128), 256>>>(mem, Wk, 0);
    rk_proj_kv<<<dim3(BB*SS/64, NHD/128), 256>>>(mem, Wv, 1);
    rk_proj_r <<<dim3((MM+63)/64, NHD/128), 256>>>(rel, Wr);
    rk_bd     <<<dim3(TT/64, (MM+127)/128, BB*NN_), 256>>>();
    rk_zdiag  <<<BB*NN_, TT>>>();
    rk_qk_mma <<<dim3(TT/128, SS/128, BB*NN_), 256>>>();
    rk_stats  <<<BB*NN_*TT, 256>>>();
    rk_pv_mma <<<dim3(TT/128, 1, BB*NN_), 256>>>();
    rk_out    <<<dim3(BB*TT/64, FF/128), 256>>>(Wout, bo, out);
}

// round 11
// speedup vs baseline: 1.6508x; 1.0576x over previous
#include <cuda_runtime.h>
#include <cuda_bf16.h>
#include <math.h>

#define BB   2
#define TT   1024
#define SS   2048
#define FF   1024
#define NN_  16
#define HH   64
#define MM   2049
#define NHD  1024

// ---- scratch (device globals; no allocations allowed) ----
static __device__ __nv_bfloat16 g_qu [BB*NN_*TT*HH];          // bf16(q + u_bias), [b][n][t][h]
static __device__ float         g_qv [BB*NN_*TT*HH];          // fp32 q + v_bias,  [b][n][t][h]
static __device__ __nv_bfloat16 g_kb [BB*NN_*SS*HH];          // bf16 k, [b][n][s][h]
static __device__ __nv_bfloat16 g_vb [BB*NN_*SS*HH];          // bf16 v, [b][n][s][h]
static __device__ float         g_r  [NN_*MM*HH];             // fp32 r, [n][m][h]
static __device__ float         g_lg [(size_t)BB*NN_*TT*SS];  // bias -> logits (256MB)
static __device__ float         g_max[BB*NN_*TT];             // softmax row max
static __device__ float         g_sum[BB*NN_*TT];             // softmax denominators
static __device__ __nv_bfloat16 g_ob [BB*TT*NHD];             // bf16 attention output, [b*t][n*h]

__device__ __forceinline__ unsigned pack_bf2(float a, float b) {
    __nv_bfloat162 p = __floats2bfloat162_rn(a, b);
    return *(unsigned*)&p;
}
__device__ __forceinline__ unsigned pack_u16(__nv_bfloat16 a, __nv_bfloat16 b) {
    unsigned short ua = *(unsigned short*)&a, ub2 = *(unsigned short*)&b;
    return (unsigned)ua | ((unsigned)ub2 << 16);
}
// split fp32 x4 into bf16 hi/lo
__device__ __forceinline__ void split4_store(float4 v, __nv_bfloat16* ph, __nv_bfloat16* pl) {
    __nv_bfloat16 h0 = __float2bfloat16(v.x), h1 = __float2bfloat16(v.y),
                  h2 = __float2bfloat16(v.z), h3 = __float2bfloat16(v.w);
    float l0 = v.x - __bfloat162float(h0), l1 = v.y - __bfloat162float(h1),
          l2 = v.z - __bfloat162float(h2), l3 = v.w - __bfloat162float(h3);
    *(uint2*)ph = make_uint2(pack_u16(h0, h1), pack_u16(h2, h3));
    *(uint2*)pl = make_uint2(pack_bf2(l0, l1), pack_bf2(l2, l3));
}

// ---- warp-level bf16 tensor-core mma (plain sm_103-safe PTX) ----
__device__ __forceinline__ void mma16816(float* d,
                                         unsigned a0, unsigned a1, unsigned a2, unsigned a3,
                                         unsigned b0, unsigned b1) {
    asm volatile(
        "mma.sync.aligned.m16n8k16.row.col.f32.bf16.bf16.f32 "
        "{%0,%1,%2,%3}, {%4,%5,%6,%7}, {%8,%9}, {%0,%1,%2,%3};"
        : "+f"(d[0]), "+f"(d[1]), "+f"(d[2]), "+f"(d[3])
        : "r"(a0), "r"(a1), "r"(a2), "r"(a3), "r"(b0), "r"(b1));
}

// =====================================================================
// FFMA GEMM skeleton: 64(M) x 128(N) tile, 256 threads, 8x4 per thread,
// K-step 16, DOUBLE-BUFFERED smem with register staging (1 sync / iter).
// Exact fp32 numerics (sequential-K fmaf accumulation, same order as R10).
// =====================================================================
#define F64_DECL() \
    __shared__ float As[2][16][72]; \
    __shared__ float Bs[2][16][132]; \
    const int tid = threadIdx.x; \
    const int ty = tid >> 5, tx = tid & 31; \
    const int a_r = tid >> 2, a_k = (tid & 3) << 2; \
    const int b_k = tid >> 4, b_c = (tid & 15) << 3; \
    float acc[8][4] = {}; \
    float4 ra, rb0, rb1;

// A fp32 row-major [M][K]; AP = base + row0*LDA; guarded by LIM rows
#define F64_LDG_A(AP, LDA, KK, LIM) { \
    ra = make_float4(0.f, 0.f, 0.f, 0.f); \
    if (a_r < (LIM)) ra = *(const float4*)((AP) + (size_t)a_r * (LDA) + (KK) + a_k); }

#define F64_STS_A(bi) { \
    As[bi][a_k][a_r] = ra.x; As[bi][a_k + 1][a_r] = ra.y; \
    As[bi][a_k + 2][a_r] = ra.z; As[bi][a_k + 3][a_r] = ra.w; }

// B fp32 row-major [K][N]; BP = base + col0
#define F64_LDG_B(BP, LDB, KK) { \
    rb0 = *(const float4*)((BP) + (size_t)((KK) + b_k) * (LDB) + b_c); \
    rb1 = *(const float4*)((BP) + (size_t)((KK) + b_k) * (LDB) + b_c + 4); }

#define F64_STS_B(bi) { \
    *(float4*)&Bs[bi][b_k][b_c] = rb0; \
    *(float4*)&Bs[bi][b_k][b_c + 4] = rb1; }

#define F64_COMPUTE(bi) { \
    _Pragma("unroll") \
    for (int k_ = 0; k_ < 16; k_++) { \
        float4 a0 = *(const float4*)&As[bi][k_][ty * 8]; \
        float4 a1 = *(const float4*)&As[bi][k_][ty * 8 + 4]; \
        float4 b  = *(const float4*)&Bs[bi][k_][tx * 4]; \
        float av[8] = {a0.x, a0.y, a0.z, a0.w, a1.x, a1.y, a1.z, a1.w}; \
        float bv[4] = {b.x, b.y, b.z, b.w}; \
        _Pragma("unroll") for (int i_ = 0; i_ < 8; i_++) \
        _Pragma("unroll") for (int j_ = 0; j_ < 4; j_++) \
            acc[i_][j_] = fmaf(av[i_], bv[j_], acc[i_][j_]); \
    } }

// Double-buffered mainloop: A fp32, B row-major fp32
#define F64_MAIN(AP, LDA, ALIM, BP, LDB, KDIM) { \
    F64_LDG_A(AP, LDA, 0, ALIM); \
    F64_LDG_B(BP, LDB, 0); \
    F64_STS_A(0); F64_STS_B(0); \
    __syncthreads(); \
    const int nIt = (KDIM) / 16; \
    for (int it = 0; it < nIt; it++) { \
        if (it + 1 < nIt) { \
            F64_LDG_A(AP, LDA, (it + 1) * 16, ALIM); \
            F64_LDG_B(BP, LDB, (it + 1) * 16); \
        } \
        F64_COMPUTE(it & 1); \
        if (it + 1 < nIt) { F64_STS_A((it + 1) & 1); F64_STS_B((it + 1) & 1); } \
        __syncthreads(); \
    } }

// =====================================================================
// Projection q: x @ Wq -> qu bf16(+ub), qv fp32(+vb), BNTH
// =====================================================================
__global__ void __launch_bounds__(256) rk_proj_q(const float* __restrict__ A,
                                                 const float* __restrict__ W,
                                                 const float* __restrict__ ub,
                                                 const float* __restrict__ vb)
{
    F64_DECL();
    const int row0 = blockIdx.x * 64, col0 = blockIdx.y * 128;
    F64_MAIN(A + (size_t)row0 * FF, FF, 1 << 30, W + col0, NHD, FF);
    const int c0 = col0 + tx * 4;
    const int n = c0 >> 6, h = c0 & 63;
    float u0 = ub[c0], u1 = ub[c0+1], u2 = ub[c0+2], u3 = ub[c0+3];
    float v0 = vb[c0], v1 = vb[c0+1], v2 = vb[c0+2], v3 = vb[c0+3];
    #pragma unroll
    for (int i = 0; i < 8; i++) {
        int r = row0 + ty * 8 + i;
        int b_ = r >> 10, t = r & 1023;
        size_t o = ((size_t)(b_ * NN_ + n) * TT + t) * HH + h;
        *(uint2*)&g_qu[o] = make_uint2(pack_bf2(acc[i][0] + u0, acc[i][1] + u1),
                                       pack_bf2(acc[i][2] + u2, acc[i][3] + u3));
        *(float4*)&g_qv[o] = make_float4(acc[i][0] + v0, acc[i][1] + v1,
                                         acc[i][2] + v2, acc[i][3] + v3);
    }
}

// =====================================================================
// Projection k / v (dst selects), BNSH bf16
// =====================================================================
__global__ void __launch_bounds__(256) rk_proj_kv(const float* __restrict__ A,
                                                  const float* __restrict__ W,
                                                  int which)
{
    F64_DECL();
    const int row0 = blockIdx.x * 64, col0 = blockIdx.y * 128;
    F64_MAIN(A + (size_t)row0 * FF, FF, 1 << 30, W + col0, NHD, FF);
    __nv_bfloat16* dst = which ? g_vb : g_kb;
    const int c0 = col0 + tx * 4;
    const int n = c0 >> 6, h = c0 & 63;
    #pragma unroll
    for (int i = 0; i < 8; i++) {
        int r = row0 + ty * 8 + i;
        int b_ = r >> 11, s = r & 2047;
        size_t o = ((size_t)(b_ * NN_ + n) * SS + s) * HH + h;
        *(uint2*)&dst[o] = make_uint2(pack_bf2(acc[i][0], acc[i][1]),
                                      pack_bf2(acc[i][2], acc[i][3]));
    }
}

// =====================================================================
// Projection r (M=2049 guard), fp32 [n][m][h]
// =====================================================================
__global__ void __launch_bounds__(256) rk_proj_r(const float* __restrict__ A,
                                                 const float* __restrict__ W)
{
    F64_DECL();
    const int row0 = blockIdx.x * 64, col0 = blockIdx.y * 128;
    const int lim = MM - row0;
    F64_MAIN(A + (size_t)row0 * FF, FF, lim, W + col0, NHD, FF);
    const int c0 = col0 + tx * 4;
    const int n = c0 >> 6, h = c0 & 63;
    #pragma unroll
    for (int i = 0; i < 8; i++) {
        int m = row0 + ty * 8 + i;
        if (m >= MM) continue;
        size_t o = ((size_t)n * MM + m) * HH + h;
        *(float4*)&g_r[o] = make_float4(acc[i][0], acc[i][1], acc[i][2], acc[i][3]);
    }
}

// =====================================================================
// bd = q_v @ r^T per (b,n), scaled, scattered through the relative shift
// B loaded transposed from [N][K]=g_r rows. Double-buffered, K-step 16.
// =====================================================================
__global__ void __launch_bounds__(256) rk_bd()
{
    F64_DECL();
    const int bn = blockIdx.z;
    const int row0 = blockIdx.x * 64, col0 = blockIdx.y * 128;
    const float* AP = g_qv + (size_t)bn * TT * HH + (size_t)row0 * HH;
    const float* BT = g_r  + (size_t)(bn & 15) * MM * HH + (size_t)col0 * HH;
    const int lim = MM - col0;
    const int t_n = tid >> 1, t_k = (tid & 1) << 3;   // B-transpose loader indices
    float4 rt0, rt1;
    // prologue
    F64_LDG_A(AP, HH, 0, 1 << 30);
    rt0 = make_float4(0.f, 0.f, 0.f, 0.f); rt1 = rt0;
    if (t_n < lim) {
        rt0 = *(const float4*)(BT + (size_t)t_n * HH + t_k);
        rt1 = *(const float4*)(BT + (size_t)t_n * HH + t_k + 4);
    }
    F64_STS_A(0);
    Bs[0][t_k + 0][t_n] = rt0.x; Bs[0][t_k + 1][t_n] = rt0.y;
    Bs[0][t_k + 2][t_n] = rt0.z; Bs[0][t_k + 3][t_n] = rt0.w;
    Bs[0][t_k + 4][t_n] = rt1.x; Bs[0][t_k + 5][t_n] = rt1.y;
    Bs[0][t_k + 6][t_n] = rt1.z; Bs[0][t_k + 7][t_n] = rt1.w;
    __syncthreads();
    const int nIt = HH / 16;
    #pragma unroll
    for (int it = 0; it < nIt; it++) {
        if (it + 1 < nIt) {
            F64_LDG_A(AP, HH, (it + 1) * 16, 1 << 30);
            rt0 = make_float4(0.f, 0.f, 0.f, 0.f); rt1 = rt0;
            if (t_n < lim) {
                rt0 = *(const float4*)(BT + (size_t)t_n * HH + (it + 1) * 16 + t_k);
                rt1 = *(const float4*)(BT + (size_t)t_n * HH + (it + 1) * 16 + t_k + 4);
            }
        }
        F64_COMPUTE(it & 1);
        if (it + 1 < nIt) {
            int bi = (it + 1) & 1;
            F64_STS_A(bi);
            Bs[bi][t_k + 0][t_n] = rt0.x; Bs[bi][t_k + 1][t_n] = rt0.y;
            Bs[bi][t_k + 2][t_n] = rt0.z; Bs[bi][t_k + 3][t_n] = rt0.w;
            Bs[bi][t_k + 4][t_n] = rt1.x; Bs[bi][t_k + 5][t_n] = rt1.y;
            Bs[bi][t_k + 6][t_n] = rt1.z; Bs[bi][t_k + 7][t_n] = rt1.w;
        }
        __syncthreads();
    }
    size_t base = (size_t)bn * TT * SS;
    #pragma unroll
    for (int i = 0; i < 8; i++) {
        int t = row0 + ty * 8 + i;
        #pragma unroll
        for (int j = 0; j < 4; j++) {
            int m = col0 + tx * 4 + j;
            if (m < MM) {
                float val = acc[i][j] * 0.125f;
                int s1 = m + t - 1023;
                if (s1 >= 0 && s1 < SS)
                    g_lg[base + (size_t)t * SS + s1] = val;
                if (t >= 1) {
                    int s2 = m + t + 1026;
                    if (s2 < SS)
                        g_lg[base + (size_t)(t - 1) * SS + s2] = val;
                }
            }
        }
    }
}

// zero the d == 1026 diagonal (never written by the scatter)
__global__ void rk_zdiag()
{
    int bn = blockIdx.x;
    int t  = threadIdx.x;
    int s  = t + 1026;
    if (s < SS)
        g_lg[(size_t)bn*TT*SS + (size_t)t*SS + s] = 0.f;
}

// =====================================================================
// final: y = fp32(out_b) @ Wout + b_out  via HMMA.
// A (g_ob) is EXACT bf16; B split into bf16 hi+lo (2 products).
// Residual error ~2^-17 relative, final output is smooth -> safe.
// 128x128 tile, 8 warps (warp tile 64x32), K-step 32.
// =====================================================================
__global__ void __launch_bounds__(256) rk_out(const float* __restrict__ Wout,
                                              const float* __restrict__ bo,
                                              float* __restrict__ out)
{
    const int tid = threadIdx.x, wid = tid >> 5, lane = tid & 31;
    const int g = lane >> 2, tg = lane & 3;
    const int m_base = (wid >> 2) * 64, n_base = (wid & 3) * 32;
    float acc[4][4][4] = {};
    const int row0 = blockIdx.x * 128, col0 = blockIdx.y * 128;
    __shared__ __nv_bfloat16 Ash[128][40];
    __shared__ __nv_bfloat16 Bsh[32][132], Bsl[32][132];
    const int ar = tid >> 1, ac0 = (tid & 1) * 16;
    const int bkr = tid >> 3, bc0 = (tid & 7) * 16;
    const __nv_bfloat16* Ag = g_ob + (size_t)row0 * NHD;
    for (int k0 = 0; k0 < NHD; k0 += 32) {
        {
            const uint4* src = (const uint4*)(Ag + (size_t)ar * NHD + k0 + ac0);
            *(uint4*)&Ash[ar][ac0] = src[0];
            *(uint4*)&Ash[ar][ac0 + 8] = src[1];
        }
        #pragma unroll
        for (int q = 0; q < 4; q++) {
            float4 v = *(const float4*)(Wout + (size_t)(k0 + bkr) * FF + col0 + bc0 + q*4);
            split4_store(v, &Bsh[bkr][bc0 + q*4], &Bsl[bkr][bc0 + q*4]);
        }
        __syncthreads();
        #pragma unroll
        for (int kk = 0; kk < 32; kk += 16) {
            unsigned ah[4][4], bh[4][2], bl[4][2];
            #pragma unroll
            for (int i_ = 0; i_ < 4; i_++) {
                int mr = m_base + i_ * 16 + g;
                ah[i_][0] = *(const unsigned*)&Ash[mr    ][kk + tg*2];
                ah[i_][1] = *(const unsigned*)&Ash[mr + 8][kk + tg*2];
                ah[i_][2] = *(const unsigned*)&Ash[mr    ][kk + 8 + tg*2];
                ah[i_][3] = *(const unsigned*)&Ash[mr + 8][kk + 8 + tg*2];
            }
            #pragma unroll
            for (int j_ = 0; j_ < 4; j_++) {
                int nr = n_base + j_ * 8 + g;
                bh[j_][0] = pack_u16(Bsh[kk + tg*2][nr],     Bsh[kk + tg*2 + 1][nr]);
                bh[j_][1] = pack_u16(Bsh[kk + 8 + tg*2][nr], Bsh[kk + 8 + tg*2 + 1][nr]);
                bl[j_][0] = pack_u16(Bsl[kk + tg*2][nr],     Bsl[kk + tg*2 + 1][nr]);
                bl[j_][1] = pack_u16(Bsl[kk + 8 + tg*2][nr], Bsl[kk + 8 + tg*2 + 1][nr]);
            }
            #pragma unroll
            for (int i_ = 0; i_ < 4; i_++)
                #pragma unroll
                for (int j_ = 0; j_ < 4; j_++) {
                    mma16816(acc[i_][j_], ah[i_][0], ah[i_][1], ah[i_][2], ah[i_][3],
                             bh[j_][0], bh[j_][1]);
                    mma16816(acc[i_][j_], ah[i_][0], ah[i_][1], ah[i_][2], ah[i_][3],
                             bl[j_][0], bl[j_][1]);
                }
        }
        __syncthreads();
    }
    #pragma unroll
    for (int i = 0; i < 4; i++) {
        int r0 = row0 + m_base + i * 16 + g;
        #pragma unroll
        for (int j = 0; j < 4; j++) {
            int c = col0 + n_base + j * 8 + tg * 2;
            float b0 = bo[c], b1 = bo[c + 1];
            #pragma unroll
            for (int hrow = 0; hrow < 2; hrow++) {
                int r = r0 + hrow * 8;
                *(float2*)&out[(size_t)r * FF + c] =
                    make_float2(acc[i][j][hrow * 2] + b0, acc[i][j][hrow * 2 + 1] + b1);
            }
        }
    }
}

// =====================================================================
// HMMA qk: logits[t,s] = bf16round(qk)*scale + bias  (RMW g_lg)
// tile 128(t) x 128(s), K=64. 8 warps: warp tile 64x32.  (R4-proven)
// =====================================================================
__global__ void __launch_bounds__(256) rk_qk_mma()
{
    __shared__ __nv_bfloat16 As[128][72];
    __shared__ __nv_bfloat16 Bs[128][72];
    const int tid = threadIdx.x, wid = tid >> 5, lane = tid & 31;
    const int g = lane >> 2, tg = lane & 3;
    const int bn = blockIdx.z;
    const int trow0 = blockIdx.x * 128, srow0 = blockIdx.y * 128;
    const int m_base = (wid >> 2) * 64, n_base = (wid & 3) * 32;

    {
        const __nv_bfloat16* Ag = g_qu + ((size_t)bn * TT + trow0) * HH;
        const __nv_bfloat16* Bg = g_kb + ((size_t)bn * SS + srow0) * HH;
        int r = tid >> 1, c0 = (tid & 1) * 32;
        const uint4* as = (const uint4*)(Ag + (size_t)r * HH + c0);
        const uint4* bs = (const uint4*)(Bg + (size_t)r * HH + c0);
        uint4* ad = (uint4*)&As[r][c0];
        uint4* bd = (uint4*)&Bs[r][c0];
        #pragma unroll
        for (int q = 0; q < 4; q++) { ad[q] = as[q]; bd[q] = bs[q]; }
    }
    __syncthreads();

    float acc[4][4][4] = {};
    #pragma unroll
    for (int kk = 0; kk < 64; kk += 16) {
        unsigned af[4][4], bf[4][2];
        #pragma unroll
        for (int i = 0; i < 4; i++) {
            int mr = m_base + i * 16 + g;
            af[i][0] = *(const unsigned*)&As[mr    ][kk + tg*2];
            af[i][1] = *(const unsigned*)&As[mr + 8][kk + tg*2];
            af[i][2] = *(const unsigned*)&As[mr    ][kk + 8 + tg*2];
            af[i][3] = *(const unsigned*)&As[mr + 8][kk + 8 + tg*2];
        }
        #pragma unroll
        for (int j = 0; j < 4; j++) {
            int nr = n_base + j * 8 + g;
            bf[j][0] = *(const unsigned*)&Bs[nr][kk + tg*2];
            bf[j][1] = *(const unsigned*)&Bs[nr][kk + 8 + tg*2];
        }
        #pragma unroll
        for (int i = 0; i < 4; i++)
            #pragma unroll
            for (int j = 0; j < 4; j++)
                mma16816(acc[i][j], af[i][0], af[i][1], af[i][2], af[i][3], bf[j][0], bf[j][1]);
    }

    size_t base = (size_t)bn * TT * SS;
    #pragma unroll
    for (int i = 0; i < 4; i++) {
        int t0 = trow0 + m_base + i * 16 + g;
        #pragma unroll
        for (int j = 0; j < 4; j++) {
            int s = srow0 + n_base + j * 8 + tg * 2;
            float q00 = __bfloat162float(__float2bfloat16(acc[i][j][0])) * 0.125f;
            float q01 = __bfloat162float(__float2bfloat16(acc[i][j][1])) * 0.125f;
            float q10 = __bfloat162float(__float2bfloat16(acc[i][j][2])) * 0.125f;
            float q11 = __bfloat162float(__float2bfloat16(acc[i][j][3])) * 0.125f;
            float2* p0 = (float2*)&g_lg[base + (size_t)t0 * SS + s];
            float2* p1 = (float2*)&g_lg[base + (size_t)(t0 + 8) * SS + s];
            float2 v0 = *p0, v1 = *p1;
            v0.x += q00; v0.y += q01;
            v1.x += q10; v1.y += q11;
            *p0 = v0; *p1 = v1;
        }
    }
}

// =====================================================================
// softmax stats: per row max + sum(exp(l - max)), single read of logits
// =====================================================================
__global__ void __launch_bounds__(256) rk_stats()
{
    const int row = blockIdx.x;
    const float* p = g_lg + (size_t)row * SS;
    __shared__ float red[256];
    const int tid = threadIdx.x;
    float r[8];
    #pragma unroll
    for (int w = 0; w < 8; w++) r[w] = p[tid + 256 * w];
    float m = r[0];
    #pragma unroll
    for (int w = 1; w < 8; w++) m = fmaxf(m, r[w]);
    red[tid] = m; __syncthreads();
    for (int off = 128; off > 0; off >>= 1) {
        if (tid < off) red[tid] = fmaxf(red[tid], red[tid + off]);
        __syncthreads();
    }
    m = red[0];
    __syncthreads();
    float s = 0.f;
    #pragma unroll
    for (int w = 0; w < 8; w++) s += expf(r[w] - m);
    red[tid] = s; __syncthreads();
    for (int off = 128; off > 0; off >>= 1) {
        if (tid < off) red[tid] += red[tid + off];
        __syncthreads();
    }
    if (tid == 0) { g_max[row] = m; g_sum[row] = red[0]; }
}

// =====================================================================
// HMMA pv: out[t,h] = bf16(probs) @ v. tile 128(t) x 64(h), K=2048 in 64-chunks.
// B fragments gathered k-major from g_vb [s][h].  (bf16-exact path)
// =====================================================================
__global__ void __launch_bounds__(256) rk_pv_mma()
{
    __shared__ __nv_bfloat16 As[128][72];
    __shared__ __nv_bfloat16 Bs[64][72];
    __shared__ float s_max[128], s_sum[128];
    const int tid = threadIdx.x, wid = tid >> 5, lane = tid & 31;
    const int g = lane >> 2, tg = lane & 3;
    const int bn = blockIdx.z;
    const int trow0 = blockIdx.x * 128;
    const int m_base = (wid >> 1) * 32, n_base = (wid & 1) * 32;

    if (tid < 128) {
        s_max[tid] = g_max[bn * TT + trow0 + tid];
        s_sum[tid] = g_sum[bn * TT + trow0 + tid];
    }
    __syncthreads();

    const float* Lg = g_lg + (size_t)bn * TT * SS + (size_t)trow0 * SS;
    const __nv_bfloat16* Vg = g_vb + (size_t)bn * SS * HH;
    const int prow = tid >> 1, pc0 = (tid & 1) * 32;
    const float mrow = s_max[prow], srow = s_sum[prow];
    const int vrow = tid >> 2, vc0 = (tid & 3) * 16;

    float acc[2][4][4] = {};
    for (int ck = 0; ck < 32; ck++) {
        const int s0 = ck * 64;
        __syncthreads();
        {
            const float4* lp = (const float4*)(Lg + (size_t)prow * SS + s0 + pc0);
            unsigned pw[16];
            #pragma unroll
            for (int q = 0; q < 8; q++) {
                float4 x = lp[q];
                float u0 = __fdiv_rn(expf(x.x - mrow), srow);
                float u1 = __fdiv_rn(expf(x.y - mrow), srow);
                float u2 = __fdiv_rn(expf(x.z - mrow), srow);
                float u3 = __fdiv_rn(expf(x.w - mrow), srow);
                pw[q*2]   = pack_bf2(u0, u1);
                pw[q*2+1] = pack_bf2(u2, u3);
            }
            uint4* dst = (uint4*)&As[prow][pc0];
            #pragma unroll
            for (int q = 0; q < 4; q++)
                dst[q] = make_uint4(pw[q*4], pw[q*4+1], pw[q*4+2], pw[q*4+3]);
        }
        {
            const uint4* vp = (const uint4*)(Vg + (size_t)(s0 + vrow) * HH + vc0);
            uint4* dst = (uint4*)&Bs[vrow][vc0];
            dst[0] = vp[0];
            dst[1] = vp[1];
        }
        __syncthreads();
        #pragma unroll
        for (int kk = 0; kk < 64; kk += 16) {
            unsigned af[2][4], bf[4][2];
            #pragma unroll
            for (int i = 0; i < 2; i++) {
                int mr = m_base + i * 16 + g;
                af[i][0] = *(const unsigned*)&As[mr    ][kk + tg*2];
                af[i][1] = *(const unsigned*)&As[mr + 8][kk + tg*2];
                af[i][2] = *(const unsigned*)&As[mr    ][kk + 8 + tg*2];
                af[i][3] = *(const unsigned*)&As[mr + 8][kk + 8 + tg*2];
            }
            #pragma unroll
            for (int j = 0; j < 4; j++) {
                int nr = n_base + j * 8 + g;
                bf[j][0] = pack_u16(Bs[kk + tg*2][nr],     Bs[kk + tg*2 + 1][nr]);
                bf[j][1] = pack_u16(Bs[kk + 8 + tg*2][nr], Bs[kk + 8 + tg*2 + 1][nr]);
            }
            #pragma unroll
            for (int i = 0; i < 2; i++)
                #pragma unroll
                for (int j = 0; j < 4; j++)
                    mma16816(acc[i][j], af[i][0], af[i][1], af[i][2], af[i][3], bf[j][0], bf[j][1]);
        }
    }

    const int b_ = bn >> 4, n = bn & 15;
    #pragma unroll
    for (int i = 0; i < 2; i++) {
        int t0 = trow0 + m_base + i * 16 + g;
        #pragma unroll
        for (int j = 0; j < 4; j++) {
            int h = n_base + j * 8 + tg * 2;
            *(unsigned*)&g_ob[(size_t)(b_ * TT + t0    ) * NHD + n * HH + h] =
                pack_bf2(acc[i][j][0], acc[i][j][1]);
            *(unsigned*)&g_ob[(size_t)(b_ * TT + t0 + 8) * NHD + n * HH + h] =
                pack_bf2(acc[i][j][2], acc[i][j][3]);
        }
    }
}

extern "C" void kernel_launch(void* const* d_in, const int* in_sizes, int n_in,
                              void* d_out, int out_size)
{
    (void)in_sizes; (void)n_in; (void)out_size;
    const float* x    = (const float*)d_in[0];
    const float* rel  = (const float*)d_in[1];
    const float* mem  = (const float*)d_in[2];
    const float* Wq   = (const float*)d_in[3];
    const float* Wk   = (const float*)d_in[4];
    const float* Wv   = (const float*)d_in[5];
    const float* Wr   = (const float*)d_in[6];
    const float* ub   = (const float*)d_in[7];
    const float* vb   = (const float*)d_in[8];
    const float* Wout = (const float*)d_in[9];
    const float* bo   = (const float*)d_in[10];
    float* out = (float*)d_out;

    rk_proj_q <<<dim3(BB*TT/64, NHD/128), 256>>>(x, Wq, ub, vb);
    rk_proj_kv<<<dim3(BB*SS/64, NHD/128), 256>>>(mem, Wk, 0);
    rk_proj_kv<<<dim3(BB*SS/64, NHD/128), 256>>>(mem, Wv, 1);
    rk_proj_r <<<dim3((MM+63)/64, NHD/128), 256>>>(rel, Wr);
    rk_bd     <<<dim3(TT/64, (MM+127)/128, BB*NN_), 256>>>();
    rk_zdiag  <<<BB*NN_, TT>>>();
    rk_qk_mma <<<dim3(TT/128, SS/128, BB*NN_), 256>>>();
    rk_stats  <<<BB*NN_*TT, 256>>>();
    rk_pv_mma <<<dim3(TT/128, 1, BB*NN_), 256>>>();
    rk_out    <<<dim3(BB*TT/128, FF/128), 256>>>(Wout, bo, out);
}

// round 12
// speedup vs baseline: 1.7414x; 1.0549x over previous
#include <cuda_runtime.h>
#include <cuda_bf16.h>
#include <math.h>

#define BB   2
#define TT   1024
#define SS   2048
#define FF   1024
#define NN_  16
#define HH   64
#define MM   2049
#define NHD  1024

// ---- scratch (device globals; no allocations allowed) ----
static __device__ __nv_bfloat16 g_qu [BB*NN_*TT*HH];          // bf16(q + u_bias), [b][n][t][h]
static __device__ float         g_qv [BB*NN_*TT*HH];          // fp32 q + v_bias,  [b][n][t][h]
static __device__ __nv_bfloat16 g_kb [BB*NN_*SS*HH];          // bf16 k, [b][n][s][h]
static __device__ __nv_bfloat16 g_vb [BB*NN_*SS*HH];          // bf16 v, [b][n][s][h]
static __device__ float         g_r  [NN_*MM*HH];             // fp32 r, [n][m][h]
static __device__ float         g_lg [(size_t)BB*NN_*TT*SS];  // bias -> logits (256MB)
static __device__ float         g_max[BB*NN_*TT];             // softmax row max
static __device__ float         g_sum[BB*NN_*TT];             // softmax denominators
static __device__ __nv_bfloat16 g_ob [BB*TT*NHD];             // bf16 attention output, [b*t][n*h]

__device__ __forceinline__ unsigned pack_bf2(float a, float b) {
    __nv_bfloat162 p = __floats2bfloat162_rn(a, b);
    return *(unsigned*)&p;
}
__device__ __forceinline__ unsigned pack_u16(__nv_bfloat16 a, __nv_bfloat16 b) {
    unsigned short ua = *(unsigned short*)&a, ub2 = *(unsigned short*)&b;
    return (unsigned)ua | ((unsigned)ub2 << 16);
}
// split fp32 x4 into bf16 hi/lo
__device__ __forceinline__ void split4_store(float4 v, __nv_bfloat16* ph, __nv_bfloat16* pl) {
    __nv_bfloat16 h0 = __float2bfloat16(v.x), h1 = __float2bfloat16(v.y),
                  h2 = __float2bfloat16(v.z), h3 = __float2bfloat16(v.w);
    float l0 = v.x - __bfloat162float(h0), l1 = v.y - __bfloat162float(h1),
          l2 = v.z - __bfloat162float(h2), l3 = v.w - __bfloat162float(h3);
    *(uint2*)ph = make_uint2(pack_u16(h0, h1), pack_u16(h2, h3));
    *(uint2*)pl = make_uint2(pack_bf2(l0, l1), pack_bf2(l2, l3));
}

// ---- warp-level bf16 tensor-core mma (plain sm_103-safe PTX) ----
__device__ __forceinline__ void mma16816(float* d,
                                         unsigned a0, unsigned a1, unsigned a2, unsigned a3,
                                         unsigned b0, unsigned b1) {
    asm volatile(
        "mma.sync.aligned.m16n8k16.row.col.f32.bf16.bf16.f32 "
        "{%0,%1,%2,%3}, {%4,%5,%6,%7}, {%8,%9}, {%0,%1,%2,%3};"
        : "+f"(d[0]), "+f"(d[1]), "+f"(d[2]), "+f"(d[3])
        : "r"(a0), "r"(a1), "r"(a2), "r"(a3), "r"(b0), "r"(b1));
}

// =====================================================================
// Shared FFMA mainloop: 64(M) x 128(N) tile, 256 threads, 8x4/thread,
// K-step 16, double-buffered. EXACT fp32 sequential-K fmaf order
// (bit-identical to R10/R11).
// =====================================================================
__device__ __forceinline__ void f64_gemm(const float* __restrict__ AP, int LDA, int ALIM,
                                         const float* __restrict__ BP, int LDB, int KDIM,
                                         float (&As)[2][16][72], float (&Bs)[2][16][132],
                                         float (&acc)[8][4])
{
    const int tid = threadIdx.x;
    const int ty = tid >> 5, tx = tid & 31;
    const int a_r = tid >> 2, a_k = (tid & 3) << 2;
    const int b_k = tid >> 4, b_c = (tid & 15) << 3;
    float4 ra, rb0, rb1;

    ra = make_float4(0.f, 0.f, 0.f, 0.f);
    if (a_r < ALIM) ra = *(const float4*)(AP + (size_t)a_r * LDA + a_k);
    rb0 = *(const float4*)(BP + (size_t)b_k * LDB + b_c);
    rb1 = *(const float4*)(BP + (size_t)b_k * LDB + b_c + 4);
    As[0][a_k][a_r] = ra.x; As[0][a_k+1][a_r] = ra.y;
    As[0][a_k+2][a_r] = ra.z; As[0][a_k+3][a_r] = ra.w;
    *(float4*)&Bs[0][b_k][b_c] = rb0;
    *(float4*)&Bs[0][b_k][b_c + 4] = rb1;
    __syncthreads();

    const int nIt = KDIM / 16;
    for (int it = 0; it < nIt; it++) {
        if (it + 1 < nIt) {
            ra = make_float4(0.f, 0.f, 0.f, 0.f);
            if (a_r < ALIM) ra = *(const float4*)(AP + (size_t)a_r * LDA + (it+1)*16 + a_k);
            rb0 = *(const float4*)(BP + (size_t)((it+1)*16 + b_k) * LDB + b_c);
            rb1 = *(const float4*)(BP + (size_t)((it+1)*16 + b_k) * LDB + b_c + 4);
        }
        const int bi = it & 1;
        #pragma unroll
        for (int k_ = 0; k_ < 16; k_++) {
            float4 a0 = *(const float4*)&As[bi][k_][ty * 8];
            float4 a1 = *(const float4*)&As[bi][k_][ty * 8 + 4];
            float4 b  = *(const float4*)&Bs[bi][k_][tx * 4];
            float av[8] = {a0.x, a0.y, a0.z, a0.w, a1.x, a1.y, a1.z, a1.w};
            float bv[4] = {b.x, b.y, b.z, b.w};
            #pragma unroll
            for (int i_ = 0; i_ < 8; i_++)
                #pragma unroll
                for (int j_ = 0; j_ < 4; j_++)
                    acc[i_][j_] = fmaf(av[i_], bv[j_], acc[i_][j_]);
        }
        if (it + 1 < nIt) {
            int nb = (it + 1) & 1;
            As[nb][a_k][a_r] = ra.x; As[nb][a_k+1][a_r] = ra.y;
            As[nb][a_k+2][a_r] = ra.z; As[nb][a_k+3][a_r] = ra.w;
            *(float4*)&Bs[nb][b_k][b_c] = rb0;
            *(float4*)&Bs[nb][b_k][b_c + 4] = rb1;
        }
        __syncthreads();
    }
}

// =====================================================================
// MERGED projection kernel: flat grid over q / k / v / r GEMMs + zdiag.
//   [0,256):    q   (32 row-blks x 8 col-blks)
//   [256,768):  k   (64 x 8)
//   [768,1280): v   (64 x 8)
//   [1280,1544):r   (33 x 8)
//   [1544,1576):zdiag (32 bn)
// =====================================================================
#define NPROJ_BLOCKS 1576
__global__ void __launch_bounds__(256) rk_projs(const float* __restrict__ x,
                                                const float* __restrict__ Wq,
                                                const float* __restrict__ ub,
                                                const float* __restrict__ vb,
                                                const float* __restrict__ mem,
                                                const float* __restrict__ Wk,
                                                const float* __restrict__ Wv,
                                                const float* __restrict__ rel,
                                                const float* __restrict__ Wr)
{
    __shared__ float As[2][16][72];
    __shared__ float Bs[2][16][132];
    const int tid = threadIdx.x;
    const int ty = tid >> 5, tx = tid & 31;
    const int id = blockIdx.x;

    if (id >= 1544) {                       // ---- zdiag ----
        int bn = id - 1544;
        for (int t = tid; t < 1022; t += 256)
            g_lg[(size_t)bn * TT * SS + (size_t)t * SS + (t + 1026)] = 0.f;
        return;
    }

    float acc[8][4] = {};

    if (id < 256) {                         // ---- q ----
        const int row0 = (id >> 3) * 64, col0 = (id & 7) * 128;
        f64_gemm(x + (size_t)row0 * FF, FF, 1 << 30, Wq + col0, NHD, FF, As, Bs, acc);
        const int c0 = col0 + tx * 4;
        const int n = c0 >> 6, h = c0 & 63;
        float u0 = ub[c0], u1 = ub[c0+1], u2 = ub[c0+2], u3 = ub[c0+3];
        float v0 = vb[c0], v1 = vb[c0+1], v2 = vb[c0+2], v3 = vb[c0+3];
        #pragma unroll
        for (int i = 0; i < 8; i++) {
            int r = row0 + ty * 8 + i;
            int b_ = r >> 10, t = r & 1023;
            size_t o = ((size_t)(b_ * NN_ + n) * TT + t) * HH + h;
            *(uint2*)&g_qu[o] = make_uint2(pack_bf2(acc[i][0] + u0, acc[i][1] + u1),
                                           pack_bf2(acc[i][2] + u2, acc[i][3] + u3));
            *(float4*)&g_qv[o] = make_float4(acc[i][0] + v0, acc[i][1] + v1,
                                             acc[i][2] + v2, acc[i][3] + v3);
        }
    } else if (id < 1280) {                 // ---- k or v ----
        const int which = (id >= 768);
        const int idx = id - (which ? 768 : 256);
        const int row0 = (idx >> 3) * 64, col0 = (idx & 7) * 128;
        const float* W = which ? Wv : Wk;
        f64_gemm(mem + (size_t)row0 * FF, FF, 1 << 30, W + col0, NHD, FF, As, Bs, acc);
        __nv_bfloat16* dst = which ? g_vb : g_kb;
        const int c0 = col0 + tx * 4;
        const int n = c0 >> 6, h = c0 & 63;
        #pragma unroll
        for (int i = 0; i < 8; i++) {
            int r = row0 + ty * 8 + i;
            int b_ = r >> 11, s = r & 2047;
            size_t o = ((size_t)(b_ * NN_ + n) * SS + s) * HH + h;
            *(uint2*)&dst[o] = make_uint2(pack_bf2(acc[i][0], acc[i][1]),
                                          pack_bf2(acc[i][2], acc[i][3]));
        }
    } else {                                // ---- r ----
        const int idx = id - 1280;
        const int row0 = (idx >> 3) * 64, col0 = (idx & 7) * 128;
        const int lim = MM - row0;
        f64_gemm(rel + (size_t)row0 * FF, FF, lim, Wr + col0, NHD, FF, As, Bs, acc);
        const int c0 = col0 + tx * 4;
        const int n = c0 >> 6, h = c0 & 63;
        #pragma unroll
        for (int i = 0; i < 8; i++) {
            int m = row0 + ty * 8 + i;
            if (m >= MM) continue;
            size_t o = ((size_t)n * MM + m) * HH + h;
            *(float4*)&g_r[o] = make_float4(acc[i][0], acc[i][1], acc[i][2], acc[i][3]);
        }
    }
}

// =====================================================================
// bd = q_v @ r^T per (b,n), scaled, scattered through the relative shift
// B loaded transposed from [N][K]=g_r rows. Double-buffered, K-step 16.
// =====================================================================
__global__ void __launch_bounds__(256) rk_bd()
{
    __shared__ float As[2][16][72];
    __shared__ float Bs[2][16][132];
    const int tid = threadIdx.x;
    const int ty = tid >> 5, tx = tid & 31;
    const int a_r = tid >> 2, a_k = (tid & 3) << 2;
    float acc[8][4] = {};
    float4 ra;
    const int bn = blockIdx.z;
    const int row0 = blockIdx.x * 64, col0 = blockIdx.y * 128;
    const float* AP = g_qv + (size_t)bn * TT * HH + (size_t)row0 * HH;
    const float* BT = g_r  + (size_t)(bn & 15) * MM * HH + (size_t)col0 * HH;
    const int lim = MM - col0;
    const int t_n = tid >> 1, t_k = (tid & 1) << 3;
    float4 rt0, rt1;
    // prologue
    ra = make_float4(0.f, 0.f, 0.f, 0.f);
    ra = *(const float4*)(AP + (size_t)a_r * HH + a_k);
    rt0 = make_float4(0.f, 0.f, 0.f, 0.f); rt1 = rt0;
    if (t_n < lim) {
        rt0 = *(const float4*)(BT + (size_t)t_n * HH + t_k);
        rt1 = *(const float4*)(BT + (size_t)t_n * HH + t_k + 4);
    }
    As[0][a_k][a_r] = ra.x; As[0][a_k+1][a_r] = ra.y;
    As[0][a_k+2][a_r] = ra.z; As[0][a_k+3][a_r] = ra.w;
    Bs[0][t_k + 0][t_n] = rt0.x; Bs[0][t_k + 1][t_n] = rt0.y;
    Bs[0][t_k + 2][t_n] = rt0.z; Bs[0][t_k + 3][t_n] = rt0.w;
    Bs[0][t_k + 4][t_n] = rt1.x; Bs[0][t_k + 5][t_n] = rt1.y;
    Bs[0][t_k + 6][t_n] = rt1.z; Bs[0][t_k + 7][t_n] = rt1.w;
    __syncthreads();
    const int nIt = HH / 16;
    #pragma unroll
    for (int it = 0; it < nIt; it++) {
        if (it + 1 < nIt) {
            ra = *(const float4*)(AP + (size_t)a_r * HH + (it + 1) * 16 + a_k);
            rt0 = make_float4(0.f, 0.f, 0.f, 0.f); rt1 = rt0;
            if (t_n < lim) {
                rt0 = *(const float4*)(BT + (size_t)t_n * HH + (it + 1) * 16 + t_k);
                rt1 = *(const float4*)(BT + (size_t)t_n * HH + (it + 1) * 16 + t_k + 4);
            }
        }
        const int bi = it & 1;
        #pragma unroll
        for (int k_ = 0; k_ < 16; k_++) {
            float4 a0 = *(const float4*)&As[bi][k_][ty * 8];
            float4 a1 = *(const float4*)&As[bi][k_][ty * 8 + 4];
            float4 b  = *(const float4*)&Bs[bi][k_][tx * 4];
            float av[8] = {a0.x, a0.y, a0.z, a0.w, a1.x, a1.y, a1.z, a1.w};
            float bv[4] = {b.x, b.y, b.z, b.w};
            #pragma unroll
            for (int i_ = 0; i_ < 8; i_++)
                #pragma unroll
                for (int j_ = 0; j_ < 4; j_++)
                    acc[i_][j_] = fmaf(av[i_], bv[j_], acc[i_][j_]);
        }
        if (it + 1 < nIt) {
            int nb = (it + 1) & 1;
            As[nb][a_k][a_r] = ra.x; As[nb][a_k+1][a_r] = ra.y;
            As[nb][a_k+2][a_r] = ra.z; As[nb][a_k+3][a_r] = ra.w;
            Bs[nb][t_k + 0][t_n] = rt0.x; Bs[nb][t_k + 1][t_n] = rt0.y;
            Bs[nb][t_k + 2][t_n] = rt0.z; Bs[nb][t_k + 3][t_n] = rt0.w;
            Bs[nb][t_k + 4][t_n] = rt1.x; Bs[nb][t_k + 5][t_n] = rt1.y;
            Bs[nb][t_k + 6][t_n] = rt1.z; Bs[nb][t_k + 7][t_n] = rt1.w;
        }
        __syncthreads();
    }
    size_t base = (size_t)bn * TT * SS;
    #pragma unroll
    for (int i = 0; i < 8; i++) {
        int t = row0 + ty * 8 + i;
        #pragma unroll
        for (int j = 0; j < 4; j++) {
            int m = col0 + tx * 4 + j;
            if (m < MM) {
                float val = acc[i][j] * 0.125f;
                int s1 = m + t - 1023;
                if (s1 >= 0 && s1 < SS)
                    g_lg[base + (size_t)t * SS + s1] = val;
                if (t >= 1) {
                    int s2 = m + t + 1026;
                    if (s2 < SS)
                        g_lg[base + (size_t)(t - 1) * SS + s2] = val;
                }
            }
        }
    }
}

// =====================================================================
// final: y = fp32(out_b) @ Wout + b_out  via HMMA (A exact bf16, B 2-term split)
// =====================================================================
__global__ void __launch_bounds__(256) rk_out(const float* __restrict__ Wout,
                                              const float* __restrict__ bo,
                                              float* __restrict__ out)
{
    const int tid = threadIdx.x, wid = tid >> 5, lane = tid & 31;
    const int g = lane >> 2, tg = lane & 3;
    const int m_base = (wid >> 2) * 64, n_base = (wid & 3) * 32;
    float acc[4][4][4] = {};
    const int row0 = blockIdx.x * 128, col0 = blockIdx.y * 128;
    __shared__ __nv_bfloat16 Ash[128][40];
    __shared__ __nv_bfloat16 Bsh[32][132], Bsl[32][132];
    const int ar = tid >> 1, ac0 = (tid & 1) * 16;
    const int bkr = tid >> 3, bc0 = (tid & 7) * 16;
    const __nv_bfloat16* Ag = g_ob + (size_t)row0 * NHD;
    for (int k0 = 0; k0 < NHD; k0 += 32) {
        {
            const uint4* src = (const uint4*)(Ag + (size_t)ar * NHD + k0 + ac0);
            *(uint4*)&Ash[ar][ac0] = src[0];
            *(uint4*)&Ash[ar][ac0 + 8] = src[1];
        }
        #pragma unroll
        for (int q = 0; q < 4; q++) {
            float4 v = *(const float4*)(Wout + (size_t)(k0 + bkr) * FF + col0 + bc0 + q*4);
            split4_store(v, &Bsh[bkr][bc0 + q*4], &Bsl[bkr][bc0 + q*4]);
        }
        __syncthreads();
        #pragma unroll
        for (int kk = 0; kk < 32; kk += 16) {
            unsigned ah[4][4], bh[4][2], bl[4][2];
            #pragma unroll
            for (int i_ = 0; i_ < 4; i_++) {
                int mr = m_base + i_ * 16 + g;
                ah[i_][0] = *(const unsigned*)&Ash[mr    ][kk + tg*2];
                ah[i_][1] = *(const unsigned*)&Ash[mr + 8][kk + tg*2];
                ah[i_][2] = *(const unsigned*)&Ash[mr    ][kk + 8 + tg*2];
                ah[i_][3] = *(const unsigned*)&Ash[mr + 8][kk + 8 + tg*2];
            }
            #pragma unroll
            for (int j_ = 0; j_ < 4; j_++) {
                int nr = n_base + j_ * 8 + g;
                bh[j_][0] = pack_u16(Bsh[kk + tg*2][nr],     Bsh[kk + tg*2 + 1][nr]);
                bh[j_][1] = pack_u16(Bsh[kk + 8 + tg*2][nr], Bsh[kk + 8 + tg*2 + 1][nr]);
                bl[j_][0] = pack_u16(Bsl[kk + tg*2][nr],     Bsl[kk + tg*2 + 1][nr]);
                bl[j_][1] = pack_u16(Bsl[kk + 8 + tg*2][nr], Bsl[kk + 8 + tg*2 + 1][nr]);
            }
            #pragma unroll
            for (int i_ = 0; i_ < 4; i_++)
                #pragma unroll
                for (int j_ = 0; j_ < 4; j_++) {
                    mma16816(acc[i_][j_], ah[i_][0], ah[i_][1], ah[i_][2], ah[i_][3],
                             bh[j_][0], bh[j_][1]);
                    mma16816(acc[i_][j_], ah[i_][0], ah[i_][1], ah[i_][2], ah[i_][3],
                             bl[j_][0], bl[j_][1]);
                }
        }
        __syncthreads();
    }
    #pragma unroll
    for (int i = 0; i < 4; i++) {
        int r0 = row0 + m_base + i * 16 + g;
        #pragma unroll
        for (int j = 0; j < 4; j++) {
            int c = col0 + n_base + j * 8 + tg * 2;
            float b0 = bo[c], b1 = bo[c + 1];
            #pragma unroll
            for (int hrow = 0; hrow < 2; hrow++) {
                int r = r0 + hrow * 8;
                *(float2*)&out[(size_t)r * FF + c] =
                    make_float2(acc[i][j][hrow * 2] + b0, acc[i][j][hrow * 2 + 1] + b1);
            }
        }
    }
}

// =====================================================================
// HMMA qk: logits[t,s] = bf16round(qk)*scale + bias  (RMW g_lg)
// =====================================================================
__global__ void __launch_bounds__(256) rk_qk_mma()
{
    __shared__ __nv_bfloat16 As[128][72];
    __shared__ __nv_bfloat16 Bs[128][72];
    const int tid = threadIdx.x, wid = tid >> 5, lane = tid & 31;
    const int g = lane >> 2, tg = lane & 3;
    const int bn = blockIdx.z;
    const int trow0 = blockIdx.x * 128, srow0 = blockIdx.y * 128;
    const int m_base = (wid >> 2) * 64, n_base = (wid & 3) * 32;

    {
        const __nv_bfloat16* Ag = g_qu + ((size_t)bn * TT + trow0) * HH;
        const __nv_bfloat16* Bg = g_kb + ((size_t)bn * SS + srow0) * HH;
        int r = tid >> 1, c0 = (tid & 1) * 32;
        const uint4* as = (const uint4*)(Ag + (size_t)r * HH + c0);
        const uint4* bs = (const uint4*)(Bg + (size_t)r * HH + c0);
        uint4* ad = (uint4*)&As[r][c0];
        uint4* bd = (uint4*)&Bs[r][c0];
        #pragma unroll
        for (int q = 0; q < 4; q++) { ad[q] = as[q]; bd[q] = bs[q]; }
    }
    __syncthreads();

    float acc[4][4][4] = {};
    #pragma unroll
    for (int kk = 0; kk < 64; kk += 16) {
        unsigned af[4][4], bf[4][2];
        #pragma unroll
        for (int i = 0; i < 4; i++) {
            int mr = m_base + i * 16 + g;
            af[i][0] = *(const unsigned*)&As[mr    ][kk + tg*2];
            af[i][1] = *(const unsigned*)&As[mr + 8][kk + tg*2];
            af[i][2] = *(const unsigned*)&As[mr    ][kk + 8 + tg*2];
            af[i][3] = *(const unsigned*)&As[mr + 8][kk + 8 + tg*2];
        }
        #pragma unroll
        for (int j = 0; j < 4; j++) {
            int nr = n_base + j * 8 + g;
            bf[j][0] = *(const unsigned*)&Bs[nr][kk + tg*2];
            bf[j][1] = *(const unsigned*)&Bs[nr][kk + 8 + tg*2];
        }
        #pragma unroll
        for (int i = 0; i < 4; i++)
            #pragma unroll
            for (int j = 0; j < 4; j++)
                mma16816(acc[i][j], af[i][0], af[i][1], af[i][2], af[i][3], bf[j][0], bf[j][1]);
    }

    size_t base = (size_t)bn * TT * SS;
    #pragma unroll
    for (int i = 0; i < 4; i++) {
        int t0 = trow0 + m_base + i * 16 + g;
        #pragma unroll
        for (int j = 0; j < 4; j++) {
            int s = srow0 + n_base + j * 8 + tg * 2;
            float q00 = __bfloat162float(__float2bfloat16(acc[i][j][0])) * 0.125f;
            float q01 = __bfloat162float(__float2bfloat16(acc[i][j][1])) * 0.125f;
            float q10 = __bfloat162float(__float2bfloat16(acc[i][j][2])) * 0.125f;
            float q11 = __bfloat162float(__float2bfloat16(acc[i][j][3])) * 0.125f;
            float2* p0 = (float2*)&g_lg[base + (size_t)t0 * SS + s];
            float2* p1 = (float2*)&g_lg[base + (size_t)(t0 + 8) * SS + s];
            float2 v0 = *p0, v1 = *p1;
            v0.x += q00; v0.y += q01;
            v1.x += q10; v1.y += q11;
            *p0 = v0; *p1 = v1;
        }
    }
}

// =====================================================================
// softmax stats: per row max + sum(exp(l - max)), single read of logits
// =====================================================================
__global__ void __launch_bounds__(256) rk_stats()
{
    const int row = blockIdx.x;
    const float* p = g_lg + (size_t)row * SS;
    __shared__ float red[256];
    const int tid = threadIdx.x;
    float r[8];
    #pragma unroll
    for (int w = 0; w < 8; w++) r[w] = p[tid + 256 * w];
    float m = r[0];
    #pragma unroll
    for (int w = 1; w < 8; w++) m = fmaxf(m, r[w]);
    red[tid] = m; __syncthreads();
    for (int off = 128; off > 0; off >>= 1) {
        if (tid < off) red[tid] = fmaxf(red[tid], red[tid + off]);
        __syncthreads();
    }
    m = red[0];
    __syncthreads();
    float s = 0.f;
    #pragma unroll
    for (int w = 0; w < 8; w++) s += expf(r[w] - m);
    red[tid] = s; __syncthreads();
    for (int off = 128; off > 0; off >>= 1) {
        if (tid < off) red[tid] += red[tid + off];
        __syncthreads();
    }
    if (tid == 0) { g_max[row] = m; g_sum[row] = red[0]; }
}

// =====================================================================
// HMMA pv: out[t,h] = bf16(probs) @ v. tile 128(t) x 64(h), K=2048 in 64-chunks.
// =====================================================================
__global__ void __launch_bounds__(256) rk_pv_mma()
{
    __shared__ __nv_bfloat16 As[128][72];
    __shared__ __nv_bfloat16 Bs[64][72];
    __shared__ float s_max[128], s_sum[128];
    const int tid = threadIdx.x, wid = tid >> 5, lane = tid & 31;
    const int g = lane >> 2, tg = lane & 3;
    const int bn = blockIdx.z;
    const int trow0 = blockIdx.x * 128;
    const int m_base = (wid >> 1) * 32, n_base = (wid & 1) * 32;

    if (tid < 128) {
        s_max[tid] = g_max[bn * TT + trow0 + tid];
        s_sum[tid] = g_sum[bn * TT + trow0 + tid];
    }
    __syncthreads();

    const float* Lg = g_lg + (size_t)bn * TT * SS + (size_t)trow0 * SS;
    const __nv_bfloat16* Vg = g_vb + (size_t)bn * SS * HH;
    const int prow = tid >> 1, pc0 = (tid & 1) * 32;
    const float mrow = s_max[prow], srow = s_sum[prow];
    const int vrow = tid >> 2, vc0 = (tid & 3) * 16;

    float acc[2][4][4] = {};
    for (int ck = 0; ck < 32; ck++) {
        const int s0 = ck * 64;
        __syncthreads();
        {
            const float4* lp = (const float4*)(Lg + (size_t)prow * SS + s0 + pc0);
            unsigned pw[16];
            #pragma unroll
            for (int q = 0; q < 8; q++) {
                float4 x = lp[q];
                float u0 = __fdiv_rn(expf(x.x - mrow), srow);
                float u1 = __fdiv_rn(expf(x.y - mrow), srow);
                float u2 = __fdiv_rn(expf(x.z - mrow), srow);
                float u3 = __fdiv_rn(expf(x.w - mrow), srow);
                pw[q*2]   = pack_bf2(u0, u1);
                pw[q*2+1] = pack_bf2(u2, u3);
            }
            uint4* dst = (uint4*)&As[prow][pc0];
            #pragma unroll
            for (int q = 0; q < 4; q++)
                dst[q] = make_uint4(pw[q*4], pw[q*4+1], pw[q*4+2], pw[q*4+3]);
        }
        {
            const uint4* vp = (const uint4*)(Vg + (size_t)(s0 + vrow) * HH + vc0);
            uint4* dst = (uint4*)&Bs[vrow][vc0];
            dst[0] = vp[0];
            dst[1] = vp[1];
        }
        __syncthreads();
        #pragma unroll
        for (int kk = 0; kk < 64; kk += 16) {
            unsigned af[2][4], bf[4][2];
            #pragma unroll
            for (int i = 0; i < 2; i++) {
                int mr = m_base + i * 16 + g;
                af[i][0] = *(const unsigned*)&As[mr    ][kk + tg*2];
                af[i][1] = *(const unsigned*)&As[mr + 8][kk + tg*2];
                af[i][2] = *(const unsigned*)&As[mr    ][kk + 8 + tg*2];
                af[i][3] = *(const unsigned*)&As[mr + 8][kk + 8 + tg*2];
            }
            #pragma unroll
            for (int j = 0; j < 4; j++) {
                int nr = n_base + j * 8 + g;
                bf[j][0] = pack_u16(Bs[kk + tg*2][nr],     Bs[kk + tg*2 + 1][nr]);
                bf[j][1] = pack_u16(Bs[kk + 8 + tg*2][nr], Bs[kk + 8 + tg*2 + 1][nr]);
            }
            #pragma unroll
            for (int i = 0; i < 2; i++)
                #pragma unroll
                for (int j = 0; j < 4; j++)
                    mma16816(acc[i][j], af[i][0], af[i][1], af[i][2], af[i][3], bf[j][0], bf[j][1]);
        }
    }

    const int b_ = bn >> 4, n = bn & 15;
    #pragma unroll
    for (int i = 0; i < 2; i++) {
        int t0 = trow0 + m_base + i * 16 + g;
        #pragma unroll
        for (int j = 0; j < 4; j++) {
            int h = n_base + j * 8 + tg * 2;
            *(unsigned*)&g_ob[(size_t)(b_ * TT + t0    ) * NHD + n * HH + h] =
                pack_bf2(acc[i][j][0], acc[i][j][1]);
            *(unsigned*)&g_ob[(size_t)(b_ * TT + t0 + 8) * NHD + n * HH + h] =
                pack_bf2(acc[i][j][2], acc[i][j][3]);
        }
    }
}

extern "C" void kernel_launch(void* const* d_in, const int* in_sizes, int n_in,
                              void* d_out, int out_size)
{
    (void)in_sizes; (void)n_in; (void)out_size;
    const float* x    = (const float*)d_in[0];
    const float* rel  = (const float*)d_in[1];
    const float* mem  = (const float*)d_in[2];
    const float* Wq   = (const float*)d_in[3];
    const float* Wk   = (const float*)d_in[4];
    const float* Wv   = (const float*)d_in[5];
    const float* Wr   = (const float*)d_in[6];
    const float* ub   = (const float*)d_in[7];
    const float* vb   = (const float*)d_in[8];
    const float* Wout = (const float*)d_in[9];
    const float* bo   = (const float*)d_in[10];
    float* out = (float*)d_out;

    rk_projs  <<<NPROJ_BLOCKS, 256>>>(x, Wq, ub, vb, mem, Wk, Wv, rel, Wr);
    rk_bd     <<<dim3(TT/64, (MM+127)/128, BB*NN_), 256>>>();
    rk_qk_mma <<<dim3(TT/128, SS/128, BB*NN_), 256>>>();
    rk_stats  <<<BB*NN_*TT, 256>>>();
    rk_pv_mma <<<dim3(TT/128, 1, BB*NN_), 256>>>();
    rk_out    <<<dim3(BB*TT/128, FF/128), 256>>>(Wout, bo, out);
}

// round 13
// speedup vs baseline: 1.9425x; 1.1155x over previous
#include <cuda_runtime.h>
#include <cuda_bf16.h>
#include <math.h>

#define BB   2
#define TT   1024
#define SS   2048
#define FF   1024
#define NN_  16
#define HH   64
#define MM   2049
#define NHD  1024

// ---- scratch (device globals; no allocations allowed) ----
static __device__ __nv_bfloat16 g_qu [BB*NN_*TT*HH];          // bf16(q + u_bias), [b][n][t][h]
static __device__ float         g_qv [BB*NN_*TT*HH];          // fp32 q + v_bias,  [b][n][t][h]
static __device__ __nv_bfloat16 g_kb [BB*NN_*SS*HH];          // bf16 k, [b][n][s][h]
static __device__ __nv_bfloat16 g_vb [BB*NN_*SS*HH];          // bf16 v, [b][n][s][h]
static __device__ float         g_r  [NN_*MM*HH];             // fp32 r, [n][m][h]
static __device__ float         g_lg [(size_t)BB*NN_*TT*SS];  // bias -> logits (256MB)
static __device__ float         g_pmax[(size_t)BB*NN_*TT*16]; // per-(row, s-block) max
static __device__ float         g_psum[(size_t)BB*NN_*TT*16]; // per-(row, s-block) sumexp
static __device__ float         g_max[BB*NN_*TT];             // softmax row max
static __device__ float         g_sum[BB*NN_*TT];             // softmax denominators
static __device__ __nv_bfloat16 g_ob [BB*TT*NHD];             // bf16 attention output, [b*t][n*h]

__device__ __forceinline__ unsigned pack_bf2(float a, float b) {
    __nv_bfloat162 p = __floats2bfloat162_rn(a, b);
    return *(unsigned*)&p;
}
__device__ __forceinline__ unsigned pack_u16(__nv_bfloat16 a, __nv_bfloat16 b) {
    unsigned short ua = *(unsigned short*)&a, ub2 = *(unsigned short*)&b;
    return (unsigned)ua | ((unsigned)ub2 << 16);
}
// split fp32 x4 into bf16 hi/lo
__device__ __forceinline__ void split4_store(float4 v, __nv_bfloat16* ph, __nv_bfloat16* pl) {
    __nv_bfloat16 h0 = __float2bfloat16(v.x), h1 = __float2bfloat16(v.y),
                  h2 = __float2bfloat16(v.z), h3 = __float2bfloat16(v.w);
    float l0 = v.x - __bfloat162float(h0), l1 = v.y - __bfloat162float(h1),
          l2 = v.z - __bfloat162float(h2), l3 = v.w - __bfloat162float(h3);
    *(uint2*)ph = make_uint2(pack_u16(h0, h1), pack_u16(h2, h3));
    *(uint2*)pl = make_uint2(pack_bf2(l0, l1), pack_bf2(l2, l3));
}

// ---- warp-level bf16 tensor-core mma (plain sm_103-safe PTX) ----
__device__ __forceinline__ void mma16816(float* d,
                                         unsigned a0, unsigned a1, unsigned a2, unsigned a3,
                                         unsigned b0, unsigned b1) {
    asm volatile(
        "mma.sync.aligned.m16n8k16.row.col.f32.bf16.bf16.f32 "
        "{%0,%1,%2,%3}, {%4,%5,%6,%7}, {%8,%9}, {%0,%1,%2,%3};"
        : "+f"(d[0]), "+f"(d[1]), "+f"(d[2]), "+f"(d[3])
        : "r"(a0), "r"(a1), "r"(a2), "r"(a3), "r"(b0), "r"(b1));
}

// =====================================================================
// Shared FFMA mainloop: 64(M) x 128(N) tile, 256 threads, 8x4/thread,
// K-step 16, double-buffered. EXACT fp32 sequential-K fmaf order.
// =====================================================================
__device__ __forceinline__ void f64_gemm(const float* __restrict__ AP, int LDA, int ALIM,
                                         const float* __restrict__ BP, int LDB, int KDIM,
                                         float (&As)[2][16][72], float (&Bs)[2][16][132],
                                         float (&acc)[8][4])
{
    const int tid = threadIdx.x;
    const int ty = tid >> 5, tx = tid & 31;
    const int a_r = tid >> 2, a_k = (tid & 3) << 2;
    const int b_k = tid >> 4, b_c = (tid & 15) << 3;
    float4 ra, rb0, rb1;

    ra = make_float4(0.f, 0.f, 0.f, 0.f);
    if (a_r < ALIM) ra = *(const float4*)(AP + (size_t)a_r * LDA + a_k);
    rb0 = *(const float4*)(BP + (size_t)b_k * LDB + b_c);
    rb1 = *(const float4*)(BP + (size_t)b_k * LDB + b_c + 4);
    As[0][a_k][a_r] = ra.x; As[0][a_k+1][a_r] = ra.y;
    As[0][a_k+2][a_r] = ra.z; As[0][a_k+3][a_r] = ra.w;
    *(float4*)&Bs[0][b_k][b_c] = rb0;
    *(float4*)&Bs[0][b_k][b_c + 4] = rb1;
    __syncthreads();

    const int nIt = KDIM / 16;
    for (int it = 0; it < nIt; it++) {
        if (it + 1 < nIt) {
            ra = make_float4(0.f, 0.f, 0.f, 0.f);
            if (a_r < ALIM) ra = *(const float4*)(AP + (size_t)a_r * LDA + (it+1)*16 + a_k);
            rb0 = *(const float4*)(BP + (size_t)((it+1)*16 + b_k) * LDB + b_c);
            rb1 = *(const float4*)(BP + (size_t)((it+1)*16 + b_k) * LDB + b_c + 4);
        }
        const int bi = it & 1;
        #pragma unroll
        for (int k_ = 0; k_ < 16; k_++) {
            float4 a0 = *(const float4*)&As[bi][k_][ty * 8];
            float4 a1 = *(const float4*)&As[bi][k_][ty * 8 + 4];
            float4 b  = *(const float4*)&Bs[bi][k_][tx * 4];
            float av[8] = {a0.x, a0.y, a0.z, a0.w, a1.x, a1.y, a1.z, a1.w};
            float bv[4] = {b.x, b.y, b.z, b.w};
            #pragma unroll
            for (int i_ = 0; i_ < 8; i_++)
                #pragma unroll
                for (int j_ = 0; j_ < 4; j_++)
                    acc[i_][j_] = fmaf(av[i_], bv[j_], acc[i_][j_]);
        }
        if (it + 1 < nIt) {
            int nb = (it + 1) & 1;
            As[nb][a_k][a_r] = ra.x; As[nb][a_k+1][a_r] = ra.y;
            As[nb][a_k+2][a_r] = ra.z; As[nb][a_k+3][a_r] = ra.w;
            *(float4*)&Bs[nb][b_k][b_c] = rb0;
            *(float4*)&Bs[nb][b_k][b_c + 4] = rb1;
        }
        __syncthreads();
    }
}

// =====================================================================
// MERGED projection kernel: flat grid over q / k / v / r GEMMs + zdiag.
// =====================================================================
#define NPROJ_BLOCKS 1576
__global__ void __launch_bounds__(256) rk_projs(const float* __restrict__ x,
                                                const float* __restrict__ Wq,
                                                const float* __restrict__ ub,
                                                const float* __restrict__ vb,
                                                const float* __restrict__ mem,
                                                const float* __restrict__ Wk,
                                                const float* __restrict__ Wv,
                                                const float* __restrict__ rel,
                                                const float* __restrict__ Wr)
{
    __shared__ float As[2][16][72];
    __shared__ float Bs[2][16][132];
    const int tid = threadIdx.x;
    const int ty = tid >> 5, tx = tid & 31;
    const int id = blockIdx.x;

    if (id >= 1544) {                       // ---- zdiag ----
        int bn = id - 1544;
        for (int t = tid; t < 1022; t += 256)
            g_lg[(size_t)bn * TT * SS + (size_t)t * SS + (t + 1026)] = 0.f;
        return;
    }

    float acc[8][4] = {};

    if (id < 256) {                         // ---- q ----
        const int row0 = (id >> 3) * 64, col0 = (id & 7) * 128;
        f64_gemm(x + (size_t)row0 * FF, FF, 1 << 30, Wq + col0, NHD, FF, As, Bs, acc);
        const int c0 = col0 + tx * 4;
        const int n = c0 >> 6, h = c0 & 63;
        float u0 = ub[c0], u1 = ub[c0+1], u2 = ub[c0+2], u3 = ub[c0+3];
        float v0 = vb[c0], v1 = vb[c0+1], v2 = vb[c0+2], v3 = vb[c0+3];
        #pragma unroll
        for (int i = 0; i < 8; i++) {
            int r = row0 + ty * 8 + i;
            int b_ = r >> 10, t = r & 1023;
            size_t o = ((size_t)(b_ * NN_ + n) * TT + t) * HH + h;
            *(uint2*)&g_qu[o] = make_uint2(pack_bf2(acc[i][0] + u0, acc[i][1] + u1),
                                           pack_bf2(acc[i][2] + u2, acc[i][3] + u3));
            *(float4*)&g_qv[o] = make_float4(acc[i][0] + v0, acc[i][1] + v1,
                                             acc[i][2] + v2, acc[i][3] + v3);
        }
    } else if (id < 1280) {                 // ---- k or v ----
        const int which = (id >= 768);
        const int idx = id - (which ? 768 : 256);
        const int row0 = (idx >> 3) * 64, col0 = (idx & 7) * 128;
        const float* W = which ? Wv : Wk;
        f64_gemm(mem + (size_t)row0 * FF, FF, 1 << 30, W + col0, NHD, FF, As, Bs, acc);
        __nv_bfloat16* dst = which ? g_vb : g_kb;
        const int c0 = col0 + tx * 4;
        const int n = c0 >> 6, h = c0 & 63;
        #pragma unroll
        for (int i = 0; i < 8; i++) {
            int r = row0 + ty * 8 + i;
            int b_ = r >> 11, s = r & 2047;
            size_t o = ((size_t)(b_ * NN_ + n) * SS + s) * HH + h;
            *(uint2*)&dst[o] = make_uint2(pack_bf2(acc[i][0], acc[i][1]),
                                          pack_bf2(acc[i][2], acc[i][3]));
        }
    } else {                                // ---- r ----
        const int idx = id - 1280;
        const int row0 = (idx >> 3) * 64, col0 = (idx & 7) * 128;
        const int lim = MM - row0;
        f64_gemm(rel + (size_t)row0 * FF, FF, lim, Wr + col0, NHD, FF, As, Bs, acc);
        const int c0 = col0 + tx * 4;
        const int n = c0 >> 6, h = c0 & 63;
        #pragma unroll
        for (int i = 0; i < 8; i++) {
            int m = row0 + ty * 8 + i;
            if (m >= MM) continue;
            size_t o = ((size_t)n * MM + m) * HH + h;
            *(float4*)&g_r[o] = make_float4(acc[i][0], acc[i][1], acc[i][2], acc[i][3]);
        }
    }
}

// =====================================================================
// bd = q_v @ r^T per (b,n), scaled, scattered through the relative shift
// =====================================================================
__global__ void __launch_bounds__(256) rk_bd()
{
    __shared__ float As[2][16][72];
    __shared__ float Bs[2][16][132];
    const int tid = threadIdx.x;
    const int ty = tid >> 5, tx = tid & 31;
    const int a_r = tid >> 2, a_k = (tid & 3) << 2;
    float acc[8][4] = {};
    float4 ra;
    const int bn = blockIdx.z;
    const int row0 = blockIdx.x * 64, col0 = blockIdx.y * 128;
    const float* AP = g_qv + (size_t)bn * TT * HH + (size_t)row0 * HH;
    const float* BT = g_r  + (size_t)(bn & 15) * MM * HH + (size_t)col0 * HH;
    const int lim = MM - col0;
    const int t_n = tid >> 1, t_k = (tid & 1) << 3;
    float4 rt0, rt1;
    ra = *(const float4*)(AP + (size_t)a_r * HH + a_k);
    rt0 = make_float4(0.f, 0.f, 0.f, 0.f); rt1 = rt0;
    if (t_n < lim) {
        rt0 = *(const float4*)(BT + (size_t)t_n * HH + t_k);
        rt1 = *(const float4*)(BT + (size_t)t_n * HH + t_k + 4);
    }
    As[0][a_k][a_r] = ra.x; As[0][a_k+1][a_r] = ra.y;
    As[0][a_k+2][a_r] = ra.z; As[0][a_k+3][a_r] = ra.w;
    Bs[0][t_k + 0][t_n] = rt0.x; Bs[0][t_k + 1][t_n] = rt0.y;
    Bs[0][t_k + 2][t_n] = rt0.z; Bs[0][t_k + 3][t_n] = rt0.w;
    Bs[0][t_k + 4][t_n] = rt1.x; Bs[0][t_k + 5][t_n] = rt1.y;
    Bs[0][t_k + 6][t_n] = rt1.z; Bs[0][t_k + 7][t_n] = rt1.w;
    __syncthreads();
    const int nIt = HH / 16;
    #pragma unroll
    for (int it = 0; it < nIt; it++) {
        if (it + 1 < nIt) {
            ra = *(const float4*)(AP + (size_t)a_r * HH + (it + 1) * 16 + a_k);
            rt0 = make_float4(0.f, 0.f, 0.f, 0.f); rt1 = rt0;
            if (t_n < lim) {
                rt0 = *(const float4*)(BT + (size_t)t_n * HH + (it + 1) * 16 + t_k);
                rt1 = *(const float4*)(BT + (size_t)t_n * HH + (it + 1) * 16 + t_k + 4);
            }
        }
        const int bi = it & 1;
        #pragma unroll
        for (int k_ = 0; k_ < 16; k_++) {
            float4 a0 = *(const float4*)&As[bi][k_][ty * 8];
            float4 a1 = *(const float4*)&As[bi][k_][ty * 8 + 4];
            float4 b  = *(const float4*)&Bs[bi][k_][tx * 4];
            float av[8] = {a0.x, a0.y, a0.z, a0.w, a1.x, a1.y, a1.z, a1.w};
            float bv[4] = {b.x, b.y, b.z, b.w};
            #pragma unroll
            for (int i_ = 0; i_ < 8; i_++)
                #pragma unroll
                for (int j_ = 0; j_ < 4; j_++)
                    acc[i_][j_] = fmaf(av[i_], bv[j_], acc[i_][j_]);
        }
        if (it + 1 < nIt) {
            int nb = (it + 1) & 1;
            As[nb][a_k][a_r] = ra.x; As[nb][a_k+1][a_r] = ra.y;
            As[nb][a_k+2][a_r] = ra.z; As[nb][a_k+3][a_r] = ra.w;
            Bs[nb][t_k + 0][t_n] = rt0.x; Bs[nb][t_k + 1][t_n] = rt0.y;
            Bs[nb][t_k + 2][t_n] = rt0.z; Bs[nb][t_k + 3][t_n] = rt0.w;
            Bs[nb][t_k + 4][t_n] = rt1.x; Bs[nb][t_k + 5][t_n] = rt1.y;
            Bs[nb][t_k + 6][t_n] = rt1.z; Bs[nb][t_k + 7][t_n] = rt1.w;
        }
        __syncthreads();
    }
    size_t base = (size_t)bn * TT * SS;
    #pragma unroll
    for (int i = 0; i < 8; i++) {
        int t = row0 + ty * 8 + i;
        #pragma unroll
        for (int j = 0; j < 4; j++) {
            int m = col0 + tx * 4 + j;
            if (m < MM) {
                float val = acc[i][j] * 0.125f;
                int s1 = m + t - 1023;
                if (s1 >= 0 && s1 < SS)
                    g_lg[base + (size_t)t * SS + s1] = val;
                if (t >= 1) {
                    int s2 = m + t + 1026;
                    if (s2 < SS)
                        g_lg[base + (size_t)(t - 1) * SS + s2] = val;
                }
            }
        }
    }
}

// =====================================================================
// final: y = fp32(out_b) @ Wout + b_out  via HMMA (A exact bf16, B 2-term split)
// =====================================================================
__global__ void __launch_bounds__(256) rk_out(const float* __restrict__ Wout,
                                              const float* __restrict__ bo,
                                              float* __restrict__ out)
{
    const int tid = threadIdx.x, wid = tid >> 5, lane = tid & 31;
    const int g = lane >> 2, tg = lane & 3;
    const int m_base = (wid >> 2) * 64, n_base = (wid & 3) * 32;
    float acc[4][4][4] = {};
    const int row0 = blockIdx.x * 128, col0 = blockIdx.y * 128;
    __shared__ __nv_bfloat16 Ash[128][40];
    __shared__ __nv_bfloat16 Bsh[32][132], Bsl[32][132];
    const int ar = tid >> 1, ac0 = (tid & 1) * 16;
    const int bkr = tid >> 3, bc0 = (tid & 7) * 16;
    const __nv_bfloat16* Ag = g_ob + (size_t)row0 * NHD;
    for (int k0 = 0; k0 < NHD; k0 += 32) {
        {
            const uint4* src = (const uint4*)(Ag + (size_t)ar * NHD + k0 + ac0);
            *(uint4*)&Ash[ar][ac0] = src[0];
            *(uint4*)&Ash[ar][ac0 + 8] = src[1];
        }
        #pragma unroll
        for (int q = 0; q < 4; q++) {
            float4 v = *(const float4*)(Wout + (size_t)(k0 + bkr) * FF + col0 + bc0 + q*4);
            split4_store(v, &Bsh[bkr][bc0 + q*4], &Bsl[bkr][bc0 + q*4]);
        }
        __syncthreads();
        #pragma unroll
        for (int kk = 0; kk < 32; kk += 16) {
            unsigned ah[4][4], bh[4][2], bl[4][2];
            #pragma unroll
            for (int i_ = 0; i_ < 4; i_++) {
                int mr = m_base + i_ * 16 + g;
                ah[i_][0] = *(const unsigned*)&Ash[mr    ][kk + tg*2];
                ah[i_][1] = *(const unsigned*)&Ash[mr + 8][kk + tg*2];
                ah[i_][2] = *(const unsigned*)&Ash[mr    ][kk + 8 + tg*2];
                ah[i_][3] = *(const unsigned*)&Ash[mr + 8][kk + 8 + tg*2];
            }
            #pragma unroll
            for (int j_ = 0; j_ < 4; j_++) {
                int nr = n_base + j_ * 8 + g;
                bh[j_][0] = pack_u16(Bsh[kk + tg*2][nr],     Bsh[kk + tg*2 + 1][nr]);
                bh[j_][1] = pack_u16(Bsh[kk + 8 + tg*2][nr], Bsh[kk + 8 + tg*2 + 1][nr]);
                bl[j_][0] = pack_u16(Bsl[kk + tg*2][nr],     Bsl[kk + tg*2 + 1][nr]);
                bl[j_][1] = pack_u16(Bsl[kk + 8 + tg*2][nr], Bsl[kk + 8 + tg*2 + 1][nr]);
            }
            #pragma unroll
            for (int i_ = 0; i_ < 4; i_++)
                #pragma unroll
                for (int j_ = 0; j_ < 4; j_++) {
                    mma16816(acc[i_][j_], ah[i_][0], ah[i_][1], ah[i_][2], ah[i_][3],
                             bh[j_][0], bh[j_][1]);
                    mma16816(acc[i_][j_], ah[i_][0], ah[i_][1], ah[i_][2], ah[i_][3],
                             bl[j_][0], bl[j_][1]);
                }
        }
        __syncthreads();
    }
    #pragma unroll
    for (int i = 0; i < 4; i++) {
        int r0 = row0 + m_base + i * 16 + g;
        #pragma unroll
        for (int j = 0; j < 4; j++) {
            int c = col0 + n_base + j * 8 + tg * 2;
            float b0 = bo[c], b1 = bo[c + 1];
            #pragma unroll
            for (int hrow = 0; hrow < 2; hrow++) {
                int r = r0 + hrow * 8;
                *(float2*)&out[(size_t)r * FF + c] =
                    make_float2(acc[i][j][hrow * 2] + b0, acc[i][j][hrow * 2 + 1] + b1);
            }
        }
    }
}

// =====================================================================
// HMMA qk + FUSED softmax partials:
// logits[t,s] = bf16round(qk)*scale + bias (RMW g_lg), then per-block
// row max / sumexp partials -> g_pmax/g_psum.
// =====================================================================
__global__ void __launch_bounds__(256) rk_qk_mma()
{
    __shared__ __nv_bfloat16 As[128][72];
    __shared__ __nv_bfloat16 Bs[128][72];
    __shared__ float sred[128][4];
    __shared__ float sbmax[128];
    const int tid = threadIdx.x, wid = tid >> 5, lane = tid & 31;
    const int g = lane >> 2, tg = lane & 3;
    const int bn = blockIdx.z;
    const int trow0 = blockIdx.x * 128, srow0 = blockIdx.y * 128;
    const int m_base = (wid >> 2) * 64, n_base = (wid & 3) * 32;
    const int nwarp = wid & 3;

    {
        const __nv_bfloat16* Ag = g_qu + ((size_t)bn * TT + trow0) * HH;
        const __nv_bfloat16* Bg = g_kb + ((size_t)bn * SS + srow0) * HH;
        int r = tid >> 1, c0 = (tid & 1) * 32;
        const uint4* as = (const uint4*)(Ag + (size_t)r * HH + c0);
        const uint4* bs = (const uint4*)(Bg + (size_t)r * HH + c0);
        uint4* ad = (uint4*)&As[r][c0];
        uint4* bd = (uint4*)&Bs[r][c0];
        #pragma unroll
        for (int q = 0; q < 4; q++) { ad[q] = as[q]; bd[q] = bs[q]; }
    }
    __syncthreads();

    float acc[4][4][4] = {};
    #pragma unroll
    for (int kk = 0; kk < 64; kk += 16) {
        unsigned af[4][4], bf[4][2];
        #pragma unroll
        for (int i = 0; i < 4; i++) {
            int mr = m_base + i * 16 + g;
            af[i][0] = *(const unsigned*)&As[mr    ][kk + tg*2];
            af[i][1] = *(const unsigned*)&As[mr + 8][kk + tg*2];
            af[i][2] = *(const unsigned*)&As[mr    ][kk + 8 + tg*2];
            af[i][3] = *(const unsigned*)&As[mr + 8][kk + 8 + tg*2];
        }
        #pragma unroll
        for (int j = 0; j < 4; j++) {
            int nr = n_base + j * 8 + g;
            bf[j][0] = *(const unsigned*)&Bs[nr][kk + tg*2];
            bf[j][1] = *(const unsigned*)&Bs[nr][kk + 8 + tg*2];
        }
        #pragma unroll
        for (int i = 0; i < 4; i++)
            #pragma unroll
            for (int j = 0; j < 4; j++)
                mma16816(acc[i][j], af[i][0], af[i][1], af[i][2], af[i][3], bf[j][0], bf[j][1]);
    }

    // RMW into g_lg; keep logit values in acc for the stats pass
    size_t base = (size_t)bn * TT * SS;
    #pragma unroll
    for (int i = 0; i < 4; i++) {
        int t0 = trow0 + m_base + i * 16 + g;
        #pragma unroll
        for (int j = 0; j < 4; j++) {
            int s = srow0 + n_base + j * 8 + tg * 2;
            float q00 = __bfloat162float(__float2bfloat16(acc[i][j][0])) * 0.125f;
            float q01 = __bfloat162float(__float2bfloat16(acc[i][j][1])) * 0.125f;
            float q10 = __bfloat162float(__float2bfloat16(acc[i][j][2])) * 0.125f;
            float q11 = __bfloat162float(__float2bfloat16(acc[i][j][3])) * 0.125f;
            float2* p0 = (float2*)&g_lg[base + (size_t)t0 * SS + s];
            float2* p1 = (float2*)&g_lg[base + (size_t)(t0 + 8) * SS + s];
            float2 v0 = *p0, v1 = *p1;
            v0.x += q00; v0.y += q01;
            v1.x += q10; v1.y += q11;
            *p0 = v0; *p1 = v1;
            acc[i][j][0] = v0.x; acc[i][j][1] = v0.y;
            acc[i][j][2] = v1.x; acc[i][j][3] = v1.y;
        }
    }

    // ---- per-row max over this block's 128 s ----
    float lm[8];
    #pragma unroll
    for (int e = 0; e < 8; e++) lm[e] = -INFINITY;
    #pragma unroll
    for (int i = 0; i < 4; i++)
        #pragma unroll
        for (int hr = 0; hr < 2; hr++) {
            int e = i * 2 + hr;
            #pragma unroll
            for (int j = 0; j < 4; j++)
                lm[e] = fmaxf(lm[e], fmaxf(acc[i][j][hr*2], acc[i][j][hr*2+1]));
        }
    #pragma unroll
    for (int e = 0; e < 8; e++) {
        lm[e] = fmaxf(lm[e], __shfl_xor_sync(0xffffffffu, lm[e], 1));
        lm[e] = fmaxf(lm[e], __shfl_xor_sync(0xffffffffu, lm[e], 2));
    }
    if (tg == 0) {
        #pragma unroll
        for (int i = 0; i < 4; i++)
            #pragma unroll
            for (int hr = 0; hr < 2; hr++)
                sred[m_base + i*16 + g + hr*8][nwarp] = lm[i*2 + hr];
    }
    __syncthreads();
    if (tid < 128) {
        float bm = fmaxf(fmaxf(sred[tid][0], sred[tid][1]),
                         fmaxf(sred[tid][2], sred[tid][3]));
        sbmax[tid] = bm;
        g_pmax[((size_t)bn * TT + trow0 + tid) * 16 + blockIdx.y] = bm;
    }
    __syncthreads();

    // ---- per-row sum of exp(l - m_blk) ----
    float ls[8];
    #pragma unroll
    for (int e = 0; e < 8; e++) ls[e] = 0.f;
    #pragma unroll
    for (int i = 0; i < 4; i++)
        #pragma unroll
        for (int hr = 0; hr < 2; hr++) {
            int e = i * 2 + hr;
            float mB = sbmax[m_base + i*16 + g + hr*8];
            #pragma unroll
            for (int j = 0; j < 4; j++)
                ls[e] += expf(acc[i][j][hr*2] - mB) + expf(acc[i][j][hr*2+1] - mB);
        }
    #pragma unroll
    for (int e = 0; e < 8; e++) {
        ls[e] += __shfl_xor_sync(0xffffffffu, ls[e], 1);
        ls[e] += __shfl_xor_sync(0xffffffffu, ls[e], 2);
    }
    __syncthreads();   // sred reuse
    if (tg == 0) {
        #pragma unroll
        for (int i = 0; i < 4; i++)
            #pragma unroll
            for (int hr = 0; hr < 2; hr++)
                sred[m_base + i*16 + g + hr*8][nwarp] = ls[i*2 + hr];
    }
    __syncthreads();
    if (tid < 128) {
        g_psum[((size_t)bn * TT + trow0 + tid) * 16 + blockIdx.y] =
            (sred[tid][0] + sred[tid][1]) + (sred[tid][2] + sred[tid][3]);
    }
}

// =====================================================================
// combine partials: m = max(m_blk), sum = sum(s_blk * exp(m_blk - m))
// =====================================================================
__global__ void __launch_bounds__(256) rk_comb()
{
    int row = blockIdx.x * 256 + threadIdx.x;   // 32768 rows
    float pm[16];
    float m = -INFINITY;
    #pragma unroll
    for (int b = 0; b < 16; b++) {
        pm[b] = g_pmax[(size_t)row * 16 + b];
        m = fmaxf(m, pm[b]);
    }
    float s = 0.f;
    #pragma unroll
    for (int b = 0; b < 16; b++)
        s += g_psum[(size_t)row * 16 + b] * expf(pm[b] - m);
    g_max[row] = m;
    g_sum[row] = s;
}

// =====================================================================
// HMMA pv: out[t,h] = bf16(probs) @ v. tile 128(t) x 64(h), K=2048 in 64-chunks.
// =====================================================================
__global__ void __launch_bounds__(256) rk_pv_mma()
{
    __shared__ __nv_bfloat16 As[128][72];
    __shared__ __nv_bfloat16 Bs[64][72];
    __shared__ float s_max[128], s_sum[128];
    const int tid = threadIdx.x, wid = tid >> 5, lane = tid & 31;
    const int g = lane >> 2, tg = lane & 3;
    const int bn = blockIdx.z;
    const int trow0 = blockIdx.x * 128;
    const int m_base = (wid >> 1) * 32, n_base = (wid & 1) * 32;

    if (tid < 128) {
        s_max[tid] = g_max[bn * TT + trow0 + tid];
        s_sum[tid] = g_sum[bn * TT + trow0 + tid];
    }
    __syncthreads();

    const float* Lg = g_lg + (size_t)bn * TT * SS + (size_t)trow0 * SS;
    const __nv_bfloat16* Vg = g_vb + (size_t)bn * SS * HH;
    const int prow = tid >> 1, pc0 = (tid & 1) * 32;
    const float mrow = s_max[prow], srow = s_sum[prow];
    const int vrow = tid >> 2, vc0 = (tid & 3) * 16;

    float acc[2][4][4] = {};
    for (int ck = 0; ck < 32; ck++) {
        const int s0 = ck * 64;
        __syncthreads();
        {
            const float4* lp = (const float4*)(Lg + (size_t)prow * SS + s0 + pc0);
            unsigned pw[16];
            #pragma unroll
            for (int q = 0; q < 8; q++) {
                float4 x = lp[q];
                float u0 = __fdiv_rn(expf(x.x - mrow), srow);
                float u1 = __fdiv_rn(expf(x.y - mrow), srow);
                float u2 = __fdiv_rn(expf(x.z - mrow), srow);
                float u3 = __fdiv_rn(expf(x.w - mrow), srow);
                pw[q*2]   = pack_bf2(u0, u1);
                pw[q*2+1] = pack_bf2(u2, u3);
            }
            uint4* dst = (uint4*)&As[prow][pc0];
            #pragma unroll
            for (int q = 0; q < 4; q++)
                dst[q] = make_uint4(pw[q*4], pw[q*4+1], pw[q*4+2], pw[q*4+3]);
        }
        {
            const uint4* vp = (const uint4*)(Vg + (size_t)(s0 + vrow) * HH + vc0);
            uint4* dst = (uint4*)&Bs[vrow][vc0];
            dst[0] = vp[0];
            dst[1] = vp[1];
        }
        __syncthreads();
        #pragma unroll
        for (int kk = 0; kk < 64; kk += 16) {
            unsigned af[2][4], bf[4][2];
            #pragma unroll
            for (int i = 0; i < 2; i++) {
                int mr = m_base + i * 16 + g;
                af[i][0] = *(const unsigned*)&As[mr    ][kk + tg*2];
                af[i][1] = *(const unsigned*)&As[mr + 8][kk + tg*2];
                af[i][2] = *(const unsigned*)&As[mr    ][kk + 8 + tg*2];
                af[i][3] = *(const unsigned*)&As[mr + 8][kk + 8 + tg*2];
            }
            #pragma unroll
            for (int j = 0; j < 4; j++) {
                int nr = n_base + j * 8 + g;
                bf[j][0] = pack_u16(Bs[kk + tg*2][nr],     Bs[kk + tg*2 + 1][nr]);
                bf[j][1] = pack_u16(Bs[kk + 8 + tg*2][nr], Bs[kk + 8 + tg*2 + 1][nr]);
            }
            #pragma unroll
            for (int i = 0; i < 2; i++)
                #pragma unroll
                for (int j = 0; j < 4; j++)
                    mma16816(acc[i][j], af[i][0], af[i][1], af[i][2], af[i][3], bf[j][0], bf[j][1]);
        }
    }

    const int b_ = bn >> 4, n = bn & 15;
    #pragma unroll
    for (int i = 0; i < 2; i++) {
        int t0 = trow0 + m_base + i * 16 + g;
        #pragma unroll
        for (int j = 0; j < 4; j++) {
            int h = n_base + j * 8 + tg * 2;
            *(unsigned*)&g_ob[(size_t)(b_ * TT + t0    ) * NHD + n * HH + h] =
                pack_bf2(acc[i][j][0], acc[i][j][1]);
            *(unsigned*)&g_ob[(size_t)(b_ * TT + t0 + 8) * NHD + n * HH + h] =
                pack_bf2(acc[i][j][2], acc[i][j][3]);
        }
    }
}

extern "C" void kernel_launch(void* const* d_in, const int* in_sizes, int n_in,
                              void* d_out, int out_size)
{
    (void)in_sizes; (void)n_in; (void)out_size;
    const float* x    = (const float*)d_in[0];
    const float* rel  = (const float*)d_in[1];
    const float* mem  = (const float*)d_in[2];
    const float* Wq   = (const float*)d_in[3];
    const float* Wk   = (const float*)d_in[4];
    const float* Wv   = (const float*)d_in[5];
    const float* Wr   = (const float*)d_in[6];
    const float* ub   = (const float*)d_in[7];
    const float* vb   = (const float*)d_in[8];
    const float* Wout = (const float*)d_in[9];
    const float* bo   = (const float*)d_in[10];
    float* out = (float*)d_out;

    rk_projs  <<<NPROJ_BLOCKS, 256>>>(x, Wq, ub, vb, mem, Wk, Wv, rel, Wr);
    rk_bd     <<<dim3(TT/64, (MM+127)/128, BB*NN_), 256>>>();
    rk_qk_mma <<<dim3(TT/128, SS/128, BB*NN_), 256>>>();
    rk_comb   <<<BB*NN_*TT/256, 256>>>();
    rk_pv_mma <<<dim3(TT/128, 1, BB*NN_), 256>>>();
    rk_out    <<<dim3(BB*TT/128, FF/128), 256>>>(Wout, bo, out);
}